// round 5
// baseline (speedup 1.0000x reference)
#include <cuda_runtime.h>
#include <math.h>

#define NN 50000
#define EE 800000
#define ETOT (EE + NN)
#define NEG_SLOPE 0.2f
#define EPS 1e-16f

// ---------------- scratch (static device globals; no allocation) ----------------
__device__ __align__(16) float g_h1[NN * 128];     // layer1 pre-aggregation features
__device__ __align__(16) float g_out1[NN * 128];   // layer1 output (post ELU)
__device__ __align__(16) float g_as1[NN * 4];      // a_src layer1
__device__ __align__(16) float g_ad1[NN * 4];      // a_dst layer1
__device__ __align__(16) float g_h2[NN * 2];
__device__ float g_as2[NN];
__device__ float g_ad2[NN];
__device__ int g_deg[NN];
__device__ int g_off[NN];
__device__ int g_cur[NN];
__device__ int g_src[ETOT];
__device__ int g_is64;    // 1 if edge_index is int64, 0 if int32
__device__ int g_total;   // running total for segment placement

// ---------------- helpers ----------------
__device__ __forceinline__ float lrelu(float x) {
    return x > 0.0f ? x : NEG_SLOPE * x;
}

__device__ __forceinline__ float warp_max(float v) {
    #pragma unroll
    for (int o = 16; o; o >>= 1) v = fmaxf(v, __shfl_xor_sync(0xFFFFFFFFu, v, o));
    return v;
}
__device__ __forceinline__ float warp_sum(float v) {
    #pragma unroll
    for (int o = 16; o; o >>= 1) v += __shfl_xor_sync(0xFFFFFFFFu, v, o);
    return v;
}

// edge index fetch honoring runtime dtype
__device__ __forceinline__ int edge_at(const void* ei, int idx, int is64) {
    if (is64) return (int)((const long long*)ei)[idx];
    return ((const int*)ei)[idx];
}

// ---------------- dtype sniff (one warp, parallel) ----------------
// int64 node ids < 2^31 have zero high words. If ANY of the first ~4K odd
// int32 words is nonzero, the buffer must be int32 (two ids per 8 bytes).
__global__ void sniff_kernel(const int* __restrict__ ei32, int nwords) {
    int lane = threadIdx.x;
    int bad = 0;
    int lim = min(nwords, 4096);
    for (int w = 1 + 2 * lane; w < lim; w += 64) {
        if (ei32[w] != 0) bad = 1;
    }
    unsigned any = __ballot_sync(0xFFFFFFFFu, bad);
    if (lane == 0) g_is64 = any ? 0 : 1;
}

// ---------------- CSR build ----------------
__global__ void init_deg_kernel(int n) {
    int i = blockIdx.x * blockDim.x + threadIdx.x;
    if (i == 0) g_total = 0;
    if (i < n) g_deg[i] = 1;  // self-loop
}

__global__ void hist_kernel(const void* __restrict__ ei, int e) {
    int i = blockIdx.x * blockDim.x + threadIdx.x;
    int is64 = g_is64;
    if (i < e) {
        int dst = edge_at(ei, e + i, is64);
        atomicAdd(&g_deg[dst], 1);
    }
}

// Fully parallel segment placement: warp-scan of degrees + one atomic per warp.
// Segments are contiguous per node but in arbitrary global order (valid for CSR use).
__global__ void offsets_kernel(int n) {
    int i = blockIdx.x * blockDim.x + threadIdx.x;
    int lane = threadIdx.x & 31;
    int d = (i < n) ? g_deg[i] : 0;
    int incl = d;
    #pragma unroll
    for (int o = 1; o < 32; o <<= 1) {
        int v = __shfl_up_sync(0xFFFFFFFFu, incl, o);
        if (lane >= o) incl += v;
    }
    int wtot = __shfl_sync(0xFFFFFFFFu, incl, 31);
    int base = 0;
    if (lane == 31) base = atomicAdd(&g_total, wtot);
    base = __shfl_sync(0xFFFFFFFFu, base, 31);
    if (i < n) {
        int st = base + incl - d;
        g_off[i] = st;
        g_cur[i] = st;
    }
}

__global__ void scatter_kernel(const void* __restrict__ ei, int e, int n) {
    int i = blockIdx.x * blockDim.x + threadIdx.x;
    int is64 = g_is64;
    if (i < e) {
        int dst = edge_at(ei, e + i, is64);
        int src = edge_at(ei, i, is64);
        int pos = atomicAdd(&g_cur[dst], 1);
        g_src[pos] = src;
    } else if (i < e + n) {
        int v = i - e;
        int pos = atomicAdd(&g_cur[v], 1);
        g_src[pos] = v;  // self loop
    }
}

// ---------------- GEMM1: h1 = x @ W1  (N x 128 @ 128 x 128) ----------------
// 256 threads, 128x128 block tile, 8x8 register microtile, K step 16
__global__ __launch_bounds__(256) void gemm1_kernel(const float* __restrict__ x,
                                                    const float* __restrict__ W1, int n) {
    __shared__ float As[16][128];   // [k][m]
    __shared__ float Bs[16][128];   // [k][n]
    int tid = threadIdx.x;
    int tx = tid & 15;              // n-dim
    int ty = tid >> 4;              // m-dim
    int row0 = blockIdx.x * 128;

    float acc[8][8];
    #pragma unroll
    for (int r = 0; r < 8; r++)
        #pragma unroll
        for (int c = 0; c < 8; c++) acc[r][c] = 0.0f;

    for (int kk = 0; kk < 8; kk++) {
        // load A tile 128 rows x 16 k (512 float4s, 2 per thread), transpose to As[k][m]
        #pragma unroll
        for (int i = 0; i < 2; i++) {
            int idx = tid + i * 256;
            int r = idx >> 2, kv = idx & 3;
            int gr = row0 + r;
            float4 v = make_float4(0.f, 0.f, 0.f, 0.f);
            if (gr < n) v = *(const float4*)&x[gr * 128 + kk * 16 + kv * 4];
            As[kv * 4 + 0][r] = v.x;
            As[kv * 4 + 1][r] = v.y;
            As[kv * 4 + 2][r] = v.z;
            As[kv * 4 + 3][r] = v.w;
        }
        // load B tile 16 k x 128 cols (512 float4s, 2 per thread)
        #pragma unroll
        for (int i = 0; i < 2; i++) {
            int idx = tid + i * 256;
            int k = idx >> 5, cv = idx & 31;
            float4 v = *(const float4*)&W1[(kk * 16 + k) * 128 + cv * 4];
            *(float4*)&Bs[k][cv * 4] = v;
        }
        __syncthreads();
        #pragma unroll
        for (int k = 0; k < 16; k++) {
            float a[8], b[8];
            *(float4*)&a[0] = *(const float4*)&As[k][ty * 8];
            *(float4*)&a[4] = *(const float4*)&As[k][ty * 8 + 4];
            *(float4*)&b[0] = *(const float4*)&Bs[k][tx * 8];
            *(float4*)&b[4] = *(const float4*)&Bs[k][tx * 8 + 4];
            #pragma unroll
            for (int r = 0; r < 8; r++)
                #pragma unroll
                for (int c = 0; c < 8; c++)
                    acc[r][c] += a[r] * b[c];
        }
        __syncthreads();
    }
    #pragma unroll
    for (int r = 0; r < 8; r++) {
        int gr = row0 + ty * 8 + r;
        if (gr < n) {
            *(float4*)&g_h1[gr * 128 + tx * 8]     = *(float4*)&acc[r][0];
            *(float4*)&g_h1[gr * 128 + tx * 8 + 4] = *(float4*)&acc[r][4];
        }
    }
}

// ---------------- attention coefficients layer 1 ----------------
__global__ void att1_kernel(const float* __restrict__ att_src1,
                            const float* __restrict__ att_dst1, int n) {
    int warp = (blockIdx.x * blockDim.x + threadIdx.x) >> 5;
    int lane = threadIdx.x & 31;
    if (warp >= n) return;
    const float* hp = g_h1 + warp * 128;
    #pragma unroll
    for (int h = 0; h < 4; h++) {
        float v = hp[h * 32 + lane];
        float ps = v * att_src1[h * 32 + lane];
        float pd = v * att_dst1[h * 32 + lane];
        ps = warp_sum(ps);
        pd = warp_sum(pd);
        if (lane == 0) {
            g_as1[warp * 4 + h] = ps;
            g_ad1[warp * 4 + h] = pd;
        }
    }
}

// ---------------- layer-1 aggregation: warp per destination node ----------------
__global__ void aggr1_kernel(const float* __restrict__ b1, int n) {
    int node = (blockIdx.x * blockDim.x + threadIdx.x) >> 5;
    int lane = threadIdx.x & 31;
    if (node >= n) return;
    int start = g_off[node], end = start + g_deg[node];
    const float4* aS = (const float4*)g_as1;
    float4 ad = ((const float4*)g_ad1)[node];

    // phase 1: per-head max over edges (lanes over edges)
    float4 m = make_float4(-INFINITY, -INFINITY, -INFINITY, -INFINITY);
    for (int i = start + lane; i < end; i += 32) {
        int s = __ldg(&g_src[i]);
        float4 as = aS[s];
        m.x = fmaxf(m.x, lrelu(as.x + ad.x));
        m.y = fmaxf(m.y, lrelu(as.y + ad.y));
        m.z = fmaxf(m.z, lrelu(as.z + ad.z));
        m.w = fmaxf(m.w, lrelu(as.w + ad.w));
    }
    m.x = warp_max(m.x); m.y = warp_max(m.y);
    m.z = warp_max(m.z); m.w = warp_max(m.w);

    // phase 2+3 merged: unnormalized weights + feature accumulation
    float acc0 = 0.f, acc1 = 0.f, acc2 = 0.f, acc3 = 0.f;
    float4 ss = make_float4(0.f, 0.f, 0.f, 0.f);
    for (int j = start; j < end; j++) {
        int s = __ldg(&g_src[j]);                 // broadcast load
        float4 as = aS[s];                        // broadcast (same addr all lanes)
        float e0 = __expf(lrelu(as.x + ad.x) - m.x);
        float e1 = __expf(lrelu(as.y + ad.y) - m.y);
        float e2 = __expf(lrelu(as.z + ad.z) - m.z);
        float e3 = __expf(lrelu(as.w + ad.w) - m.w);
        ss.x += e0; ss.y += e1; ss.z += e2; ss.w += e3;
        const float* hp = g_h1 + s * 128 + lane;
        acc0 += e0 * hp[0];
        acc1 += e1 * hp[32];
        acc2 += e2 * hp[64];
        acc3 += e3 * hp[96];
    }
    float o0 = acc0 / (ss.x + EPS) + b1[lane];
    float o1 = acc1 / (ss.y + EPS) + b1[32 + lane];
    float o2 = acc2 / (ss.z + EPS) + b1[64 + lane];
    float o3 = acc3 / (ss.w + EPS) + b1[96 + lane];
    // ELU
    o0 = o0 > 0.f ? o0 : (__expf(o0) - 1.0f);
    o1 = o1 > 0.f ? o1 : (__expf(o1) - 1.0f);
    o2 = o2 > 0.f ? o2 : (__expf(o2) - 1.0f);
    o3 = o3 > 0.f ? o3 : (__expf(o3) - 1.0f);
    float* op = g_out1 + node * 128 + lane;
    op[0] = o0; op[32] = o1; op[64] = o2; op[96] = o3;
}

// ---------------- layer 2: GEMM (128->2) + attention coefficients ----------------
__global__ void gemm2att_kernel(const float* __restrict__ W2,
                                const float* __restrict__ att_src2,
                                const float* __restrict__ att_dst2, int n) {
    int node = (blockIdx.x * blockDim.x + threadIdx.x) >> 5;
    int lane = threadIdx.x & 31;
    if (node >= n) return;
    float a0 = 0.f, a1 = 0.f;
    const float* op = g_out1 + node * 128;
    #pragma unroll
    for (int j = 0; j < 4; j++) {
        int k = lane + 32 * j;
        float v = op[k];
        a0 += v * __ldg(&W2[k * 2 + 0]);
        a1 += v * __ldg(&W2[k * 2 + 1]);
    }
    a0 = warp_sum(a0);
    a1 = warp_sum(a1);
    if (lane == 0) {
        g_h2[node * 2 + 0] = a0;
        g_h2[node * 2 + 1] = a1;
        g_as2[node] = a0 * att_src2[0] + a1 * att_src2[1];
        g_ad2[node] = a0 * att_dst2[0] + a1 * att_dst2[1];
    }
}

// ---------------- layer-2 aggregation + bias + log_softmax ----------------
__global__ void aggr2_kernel(const float* __restrict__ b2,
                             float* __restrict__ out, int n) {
    int node = (blockIdx.x * blockDim.x + threadIdx.x) >> 5;
    int lane = threadIdx.x & 31;
    if (node >= n) return;
    int start = g_off[node], end = start + g_deg[node];
    float ad = g_ad2[node];

    float m = -INFINITY;
    for (int i = start + lane; i < end; i += 32) {
        int s = __ldg(&g_src[i]);
        m = fmaxf(m, lrelu(g_as2[s] + ad));
    }
    m = warp_max(m);

    float sum = 0.f, acc0 = 0.f, acc1 = 0.f;
    for (int i = start + lane; i < end; i += 32) {
        int s = __ldg(&g_src[i]);
        float ex = __expf(lrelu(g_as2[s] + ad) - m);
        sum += ex;
        acc0 += ex * g_h2[s * 2 + 0];
        acc1 += ex * g_h2[s * 2 + 1];
    }
    sum = warp_sum(sum);
    acc0 = warp_sum(acc0);
    acc1 = warp_sum(acc1);

    if (lane == 0) {
        float o0 = acc0 / (sum + EPS) + b2[0];
        float o1 = acc1 / (sum + EPS) + b2[1];
        float mx = fmaxf(o0, o1);
        float lse = mx + __logf(__expf(o0 - mx) + __expf(o1 - mx));
        out[node * 2 + 0] = o0 - lse;
        out[node * 2 + 1] = o1 - lse;
    }
}

// ---------------- launch ----------------
extern "C" void kernel_launch(void* const* d_in, const int* in_sizes, int n_in,
                              void* d_out, int out_size) {
    const float* x         = (const float*)d_in[0];
    const void*  ei        = (const void*)d_in[1];
    const float* W1        = (const float*)d_in[2];
    const float* att_src1  = (const float*)d_in[3];
    const float* att_dst1  = (const float*)d_in[4];
    const float* b1        = (const float*)d_in[5];
    const float* W2        = (const float*)d_in[6];
    const float* att_src2  = (const float*)d_in[7];
    const float* att_dst2  = (const float*)d_in[8];
    const float* b2        = (const float*)d_in[9];
    float* out             = (float*)d_out;

    int n = in_sizes[0] / 128;   // 50000
    int e = in_sizes[1] / 2;     // 800000

    sniff_kernel<<<1, 32>>>((const int*)ei, in_sizes[1]);
    init_deg_kernel<<<(n + 255) / 256, 256>>>(n);
    hist_kernel<<<(e + 255) / 256, 256>>>(ei, e);
    offsets_kernel<<<(n + 255) / 256, 256>>>(n);
    scatter_kernel<<<(e + n + 255) / 256, 256>>>(ei, e, n);

    gemm1_kernel<<<(n + 127) / 128, 256>>>(x, W1, n);
    att1_kernel<<<(n * 32 + 255) / 256, 256>>>(att_src1, att_dst1, n);
    aggr1_kernel<<<(n * 32 + 255) / 256, 256>>>(b1, n);
    gemm2att_kernel<<<(n * 32 + 255) / 256, 256>>>(W2, att_src2, att_dst2, n);
    aggr2_kernel<<<(n * 32 + 255) / 256, 256>>>(b2, out, n);
}

// round 6
// speedup vs baseline: 1.4787x; 1.4787x over previous
#include <cuda_runtime.h>
#include <math.h>

#define NN 50000
#define EE 800000
#define ETOT (EE + NN)
#define NEG_SLOPE 0.2f
#define EPS 1e-16f
#define FULLMASK 0xFFFFFFFFu

// ---------------- scratch (static device globals; no allocation) ----------------
__device__ __align__(16) float g_h1[NN * 128];     // layer1 pre-aggregation features
__device__ __align__(16) float g_out1[NN * 128];   // layer1 output (post ELU)
__device__ __align__(16) float g_as1[NN * 4];      // a_src layer1
__device__ __align__(16) float g_ad1[NN * 4];      // a_dst layer1
__device__ __align__(16) float g_h2[NN * 2];
__device__ float g_as2[NN];
__device__ float g_ad2[NN];
__device__ int g_deg[NN];
__device__ int g_off[NN];
__device__ int g_cur[NN];
__device__ int g_src[ETOT];
__device__ int g_is64;              // 1 if edge_index is int64, 0 if int32
__device__ int g_total;             // running total for segment placement
__device__ unsigned g_maxenc1[4];   // encoded global max of a_src per head (layer1)
__device__ unsigned g_maxenc2;      // encoded global max of a_src (layer2)

// ---------------- helpers ----------------
__device__ __forceinline__ float lrelu(float x) {
    return x > 0.0f ? x : NEG_SLOPE * x;
}
__device__ __forceinline__ float warp_sum(float v) {
    #pragma unroll
    for (int o = 16; o; o >>= 1) v += __shfl_xor_sync(FULLMASK, v, o);
    return v;
}
// order-preserving float<->uint encoding for atomicMax
__device__ __forceinline__ unsigned fenc(float f) {
    unsigned b = __float_as_uint(f);
    return (b & 0x80000000u) ? ~b : (b | 0x80000000u);
}
__device__ __forceinline__ float fdec(unsigned u) {
    return (u & 0x80000000u) ? __uint_as_float(u ^ 0x80000000u)
                             : __uint_as_float(~u);
}
// edge index fetch honoring runtime dtype
__device__ __forceinline__ int edge_at(const void* ei, int idx, int is64) {
    if (is64) return (int)((const long long*)ei)[idx];
    return ((const int*)ei)[idx];
}

// ---------------- dtype sniff (one warp, parallel) ----------------
__global__ void sniff_kernel(const int* __restrict__ ei32, int nwords) {
    int lane = threadIdx.x;
    int bad = 0;
    int lim = min(nwords, 4096);
    for (int w = 1 + 2 * lane; w < lim; w += 64) {
        if (ei32[w] != 0) bad = 1;
    }
    unsigned any = __ballot_sync(FULLMASK, bad);
    if (lane == 0) g_is64 = any ? 0 : 1;
}

// ---------------- CSR build ----------------
__global__ void init_deg_kernel(int n) {
    int i = blockIdx.x * blockDim.x + threadIdx.x;
    if (i == 0) g_total = 0;
    if (i < 4) g_maxenc1[i] = 0;
    if (i == 5) g_maxenc2 = 0;
    if (i < n) g_deg[i] = 1;  // self-loop
}

__global__ void hist_kernel(const void* __restrict__ ei, int e) {
    int i = blockIdx.x * blockDim.x + threadIdx.x;
    int is64 = g_is64;
    if (i < e) {
        int dst = edge_at(ei, e + i, is64);
        atomicAdd(&g_deg[dst], 1);
    }
}

// warp-scan of degrees + one atomic per warp; segments contiguous per node,
// arbitrary global order (valid CSR).
__global__ void offsets_kernel(int n) {
    int i = blockIdx.x * blockDim.x + threadIdx.x;
    int lane = threadIdx.x & 31;
    int d = (i < n) ? g_deg[i] : 0;
    int incl = d;
    #pragma unroll
    for (int o = 1; o < 32; o <<= 1) {
        int v = __shfl_up_sync(FULLMASK, incl, o);
        if (lane >= o) incl += v;
    }
    int wtot = __shfl_sync(FULLMASK, incl, 31);
    int base = 0;
    if (lane == 31) base = atomicAdd(&g_total, wtot);
    base = __shfl_sync(FULLMASK, base, 31);
    if (i < n) {
        int st = base + incl - d;
        g_off[i] = st;
        g_cur[i] = st;
    }
}

__global__ void scatter_kernel(const void* __restrict__ ei, int e, int n) {
    int i = blockIdx.x * blockDim.x + threadIdx.x;
    int is64 = g_is64;
    if (i < e) {
        int dst = edge_at(ei, e + i, is64);
        int src = edge_at(ei, i, is64);
        int pos = atomicAdd(&g_cur[dst], 1);
        g_src[pos] = src;
    } else if (i < e + n) {
        int v = i - e;
        int pos = atomicAdd(&g_cur[v], 1);
        g_src[pos] = v;  // self loop
    }
}

// ---------------- GEMM1: h1 = x @ W1  (N x 128 @ 128 x 128) ----------------
// 256 threads, 128x128 block tile, 2x2 groups of 4x4 microtile (conflict-free LDS)
__global__ __launch_bounds__(256) void gemm1_kernel(const float* __restrict__ x,
                                                    const float* __restrict__ W1, int n) {
    __shared__ float As[16][128];   // [k][m]
    __shared__ float Bs[16][128];   // [k][n]
    int tid = threadIdx.x;
    int tx = tid & 15;              // n-dim (cols tx*4 and 64+tx*4)
    int ty = tid >> 4;              // m-dim (rows ty*4 and 64+ty*4)
    int row0 = blockIdx.x * 128;

    float acc[2][4][2][4];          // [rhalf][r][chalf][c]
    #pragma unroll
    for (int rh = 0; rh < 2; rh++)
        #pragma unroll
        for (int r = 0; r < 4; r++)
            #pragma unroll
            for (int ch = 0; ch < 2; ch++)
                #pragma unroll
                for (int c = 0; c < 4; c++) acc[rh][r][ch][c] = 0.0f;

    for (int kk = 0; kk < 8; kk++) {
        // load A tile 128 rows x 16 k (512 float4s, 2 per thread), transpose to As[k][m]
        #pragma unroll
        for (int i = 0; i < 2; i++) {
            int idx = tid + i * 256;
            int r = idx >> 2, kv = idx & 3;
            int gr = row0 + r;
            float4 v = make_float4(0.f, 0.f, 0.f, 0.f);
            if (gr < n) v = *(const float4*)&x[gr * 128 + kk * 16 + kv * 4];
            As[kv * 4 + 0][r] = v.x;
            As[kv * 4 + 1][r] = v.y;
            As[kv * 4 + 2][r] = v.z;
            As[kv * 4 + 3][r] = v.w;
        }
        // load B tile 16 k x 128 cols (512 float4s, 2 per thread)
        #pragma unroll
        for (int i = 0; i < 2; i++) {
            int idx = tid + i * 256;
            int k = idx >> 5, cv = idx & 31;
            *(float4*)&Bs[k][cv * 4] = *(const float4*)&W1[(kk * 16 + k) * 128 + cv * 4];
        }
        __syncthreads();
        #pragma unroll
        for (int k = 0; k < 16; k++) {
            float4 a0 = *(const float4*)&As[k][ty * 4];        // broadcast
            float4 a1 = *(const float4*)&As[k][64 + ty * 4];   // broadcast
            float4 b0 = *(const float4*)&Bs[k][tx * 4];        // 16B/lane, conflict-free
            float4 b1 = *(const float4*)&Bs[k][64 + tx * 4];
            float av[2][4] = {{a0.x, a0.y, a0.z, a0.w}, {a1.x, a1.y, a1.z, a1.w}};
            float bv[2][4] = {{b0.x, b0.y, b0.z, b0.w}, {b1.x, b1.y, b1.z, b1.w}};
            #pragma unroll
            for (int rh = 0; rh < 2; rh++)
                #pragma unroll
                for (int r = 0; r < 4; r++)
                    #pragma unroll
                    for (int ch = 0; ch < 2; ch++)
                        #pragma unroll
                        for (int c = 0; c < 4; c++)
                            acc[rh][r][ch][c] = fmaf(av[rh][r], bv[ch][c], acc[rh][r][ch][c]);
        }
        __syncthreads();
    }
    #pragma unroll
    for (int rh = 0; rh < 2; rh++) {
        #pragma unroll
        for (int r = 0; r < 4; r++) {
            int gr = row0 + rh * 64 + ty * 4 + r;
            if (gr < n) {
                *(float4*)&g_h1[gr * 128 + tx * 4]      = *(float4*)&acc[rh][r][0][0];
                *(float4*)&g_h1[gr * 128 + 64 + tx * 4] = *(float4*)&acc[rh][r][1][0];
            }
        }
    }
}

// ---------------- attention coefficients layer 1 (+ global max of a_src) ----------------
__global__ void att1_kernel(const float* __restrict__ att_src1,
                            const float* __restrict__ att_dst1, int n) {
    __shared__ unsigned sm[4];
    if (threadIdx.x < 4) sm[threadIdx.x] = 0;
    __syncthreads();
    int node = (blockIdx.x * blockDim.x + threadIdx.x) >> 5;
    int lane = threadIdx.x & 31;
    if (node < n) {
        const float* hp = g_h1 + node * 128;
        #pragma unroll
        for (int h = 0; h < 4; h++) {
            float v = hp[h * 32 + lane];
            float ps = v * att_src1[h * 32 + lane];
            float pd = v * att_dst1[h * 32 + lane];
            ps = warp_sum(ps);
            pd = warp_sum(pd);
            if (lane == 0) {
                g_as1[node * 4 + h] = ps;
                g_ad1[node * 4 + h] = pd;
                atomicMax(&sm[h], fenc(ps));
            }
        }
    }
    __syncthreads();
    if (threadIdx.x < 4) atomicMax(&g_maxenc1[threadIdx.x], sm[threadIdx.x]);
}

// ---------------- layer-1 aggregation: warp per destination node, single pass ----------------
__global__ void aggr1_kernel(const float* __restrict__ b1, int n) {
    int node = (blockIdx.x * blockDim.x + threadIdx.x) >> 5;
    int lane = threadIdx.x & 31;
    if (node >= n) return;
    int start = g_off[node], end = start + g_deg[node];
    const float4* aS = (const float4*)g_as1;
    float4 ad = ((const float4*)g_ad1)[node];

    // upper-bound shift: M >= all e for this node (softmax is shift-invariant)
    float4 M;
    M.x = lrelu(fdec(g_maxenc1[0]) + ad.x);
    M.y = lrelu(fdec(g_maxenc1[1]) + ad.y);
    M.z = lrelu(fdec(g_maxenc1[2]) + ad.z);
    M.w = lrelu(fdec(g_maxenc1[3]) + ad.w);

    float acc0 = 0.f, acc1 = 0.f, acc2 = 0.f, acc3 = 0.f;
    float ss0 = 0.f, ss1 = 0.f, ss2 = 0.f, ss3 = 0.f;

    for (int base = start; base < end; base += 32) {
        int cnt = min(32, end - base);
        int s = 0;
        float e0 = 0.f, e1 = 0.f, e2 = 0.f, e3 = 0.f;
        if (lane < cnt) {
            s = __ldg(&g_src[base + lane]);
            float4 as = aS[s];
            e0 = __expf(lrelu(as.x + ad.x) - M.x);
            e1 = __expf(lrelu(as.y + ad.y) - M.y);
            e2 = __expf(lrelu(as.z + ad.z) - M.z);
            e3 = __expf(lrelu(as.w + ad.w) - M.w);
        }
        for (int j = 0; j < cnt; j++) {
            int sj   = __shfl_sync(FULLMASK, s, j);
            float f0 = __shfl_sync(FULLMASK, e0, j);
            float f1 = __shfl_sync(FULLMASK, e1, j);
            float f2 = __shfl_sync(FULLMASK, e2, j);
            float f3 = __shfl_sync(FULLMASK, e3, j);
            ss0 += f0; ss1 += f1; ss2 += f2; ss3 += f3;
            const float* hp = g_h1 + sj * 128 + lane;
            acc0 = fmaf(f0, hp[0],  acc0);
            acc1 = fmaf(f1, hp[32], acc1);
            acc2 = fmaf(f2, hp[64], acc2);
            acc3 = fmaf(f3, hp[96], acc3);
        }
    }
    float o0 = acc0 / (ss0 + EPS) + b1[lane];
    float o1 = acc1 / (ss1 + EPS) + b1[32 + lane];
    float o2 = acc2 / (ss2 + EPS) + b1[64 + lane];
    float o3 = acc3 / (ss3 + EPS) + b1[96 + lane];
    // ELU
    o0 = o0 > 0.f ? o0 : (__expf(o0) - 1.0f);
    o1 = o1 > 0.f ? o1 : (__expf(o1) - 1.0f);
    o2 = o2 > 0.f ? o2 : (__expf(o2) - 1.0f);
    o3 = o3 > 0.f ? o3 : (__expf(o3) - 1.0f);
    float* op = g_out1 + node * 128 + lane;
    op[0] = o0; op[32] = o1; op[64] = o2; op[96] = o3;
}

// ---------------- layer 2: GEMM (128->2) + attention coefficients (+ max) ----------------
__global__ void gemm2att_kernel(const float* __restrict__ W2,
                                const float* __restrict__ att_src2,
                                const float* __restrict__ att_dst2, int n) {
    __shared__ unsigned sm;
    if (threadIdx.x == 0) sm = 0;
    __syncthreads();
    int node = (blockIdx.x * blockDim.x + threadIdx.x) >> 5;
    int lane = threadIdx.x & 31;
    if (node < n) {
        float a0 = 0.f, a1 = 0.f;
        const float* op = g_out1 + node * 128;
        #pragma unroll
        for (int j = 0; j < 4; j++) {
            int k = lane + 32 * j;
            float v = op[k];
            a0 += v * __ldg(&W2[k * 2 + 0]);
            a1 += v * __ldg(&W2[k * 2 + 1]);
        }
        a0 = warp_sum(a0);
        a1 = warp_sum(a1);
        if (lane == 0) {
            g_h2[node * 2 + 0] = a0;
            g_h2[node * 2 + 1] = a1;
            float as2 = a0 * att_src2[0] + a1 * att_src2[1];
            g_as2[node] = as2;
            g_ad2[node] = a0 * att_dst2[0] + a1 * att_dst2[1];
            atomicMax(&sm, fenc(as2));
        }
    }
    __syncthreads();
    if (threadIdx.x == 0) atomicMax(&g_maxenc2, sm);
}

// ---------------- layer-2 aggregation + bias + log_softmax (single pass) ----------------
__global__ void aggr2_kernel(const float* __restrict__ b2,
                             float* __restrict__ out, int n) {
    int node = (blockIdx.x * blockDim.x + threadIdx.x) >> 5;
    int lane = threadIdx.x & 31;
    if (node >= n) return;
    int start = g_off[node], end = start + g_deg[node];
    float ad = g_ad2[node];
    float M = lrelu(fdec(g_maxenc2) + ad);

    float sum = 0.f, acc0 = 0.f, acc1 = 0.f;
    for (int i = start + lane; i < end; i += 32) {
        int s = __ldg(&g_src[i]);
        float ex = __expf(lrelu(g_as2[s] + ad) - M);
        sum += ex;
        acc0 += ex * g_h2[s * 2 + 0];
        acc1 += ex * g_h2[s * 2 + 1];
    }
    sum = warp_sum(sum);
    acc0 = warp_sum(acc0);
    acc1 = warp_sum(acc1);

    if (lane == 0) {
        float o0 = acc0 / (sum + EPS) + b2[0];
        float o1 = acc1 / (sum + EPS) + b2[1];
        float mx = fmaxf(o0, o1);
        float lse = mx + __logf(__expf(o0 - mx) + __expf(o1 - mx));
        out[node * 2 + 0] = o0 - lse;
        out[node * 2 + 1] = o1 - lse;
    }
}

// ---------------- launch ----------------
extern "C" void kernel_launch(void* const* d_in, const int* in_sizes, int n_in,
                              void* d_out, int out_size) {
    const float* x         = (const float*)d_in[0];
    const void*  ei        = (const void*)d_in[1];
    const float* W1        = (const float*)d_in[2];
    const float* att_src1  = (const float*)d_in[3];
    const float* att_dst1  = (const float*)d_in[4];
    const float* b1        = (const float*)d_in[5];
    const float* W2        = (const float*)d_in[6];
    const float* att_src2  = (const float*)d_in[7];
    const float* att_dst2  = (const float*)d_in[8];
    const float* b2        = (const float*)d_in[9];
    float* out             = (float*)d_out;

    int n = in_sizes[0] / 128;   // 50000
    int e = in_sizes[1] / 2;     // 800000

    sniff_kernel<<<1, 32>>>((const int*)ei, in_sizes[1]);
    init_deg_kernel<<<(n + 255) / 256, 256>>>(n);
    hist_kernel<<<(e + 255) / 256, 256>>>(ei, e);
    offsets_kernel<<<(n + 255) / 256, 256>>>(n);
    scatter_kernel<<<(e + n + 255) / 256, 256>>>(ei, e, n);

    gemm1_kernel<<<(n + 127) / 128, 256>>>(x, W1, n);
    att1_kernel<<<(n * 32 + 255) / 256, 256>>>(att_src1, att_dst1, n);
    aggr1_kernel<<<(n * 32 + 255) / 256, 256>>>(b1, n);
    gemm2att_kernel<<<(n * 32 + 255) / 256, 256>>>(W2, att_src2, att_dst2, n);
    aggr2_kernel<<<(n * 32 + 255) / 256, 256>>>(b2, out, n);
}

// round 8
// speedup vs baseline: 1.8353x; 1.2412x over previous
#include <cuda_runtime.h>
#include <cuda_fp16.h>
#include <math.h>

#define NN 50000
#define EE 800000
#define ETOT (EE + NN)
#define NEG_SLOPE 0.2f
#define EPS 1e-16f
#define FULLMASK 0xFFFFFFFFu

// ---------------- scratch (static device globals; no allocation) ----------------
__device__ __align__(16) __half g_h1h[NN * 128];   // layer1 features, fp16 (gather payload)
__device__ __align__(16) float g_out1[NN * 128];   // layer1 output (post ELU), fp32
__device__ __align__(16) float g_as1[NN * 4];      // a_src layer1 (exact fp32)
__device__ __align__(16) float g_ad1[NN * 4];      // a_dst layer1
__device__ __align__(16) float g_h2[NN * 2];
__device__ float g_as2[NN];
__device__ float g_ad2[NN];
__device__ int g_deg[NN];
__device__ int g_off[NN];
__device__ int g_cur[NN];
__device__ int g_src[ETOT];
__device__ int g_is64;
__device__ int g_total;
__device__ unsigned g_maxenc1[4];   // encoded global max of a_src per head (layer1)
__device__ unsigned g_maxenc2;

// ---------------- helpers ----------------
__device__ __forceinline__ float lrelu(float x) {
    return x > 0.0f ? x : NEG_SLOPE * x;
}
__device__ __forceinline__ float warp_sum(float v) {
    #pragma unroll
    for (int o = 16; o; o >>= 1) v += __shfl_xor_sync(FULLMASK, v, o);
    return v;
}
// order-preserving float<->uint encoding for atomicMax
__device__ __forceinline__ unsigned fenc(float f) {
    unsigned b = __float_as_uint(f);
    return (b & 0x80000000u) ? ~b : (b | 0x80000000u);
}
__device__ __forceinline__ float fdec(unsigned u) {
    return (u & 0x80000000u) ? __uint_as_float(u ^ 0x80000000u)
                             : __uint_as_float(~u);
}
__device__ __forceinline__ int edge_at(const void* ei, int idx, int is64) {
    if (is64) return (int)((const long long*)ei)[idx];
    return ((const int*)ei)[idx];
}
// packed fp32x2 FMA (Blackwell): d = a*b + d, two lanes at once
__device__ __forceinline__ unsigned long long pk2(float lo, float hi) {
    unsigned long long r;
    asm("mov.b64 %0, {%1, %2};" : "=l"(r)
        : "r"(__float_as_uint(lo)), "r"(__float_as_uint(hi)));
    return r;
}
__device__ __forceinline__ float2 upk2(unsigned long long v) {
    unsigned lo, hi;
    asm("mov.b64 {%0, %1}, %2;" : "=r"(lo), "=r"(hi) : "l"(v));
    return make_float2(__uint_as_float(lo), __uint_as_float(hi));
}
__device__ __forceinline__ void fma2(unsigned long long& d,
                                     unsigned long long a, unsigned long long b) {
    asm("fma.rn.f32x2 %0, %1, %2, %0;" : "+l"(d) : "l"(a), "l"(b));
}

// ---------------- K1: init + dtype sniff ----------------
__global__ void init_sniff_kernel(const int* __restrict__ ei32, int nwords, int n) {
    int i = blockIdx.x * blockDim.x + threadIdx.x;
    if (i == 0) g_total = 0;
    if (i < 4) g_maxenc1[i] = 0;
    if (i == 5) g_maxenc2 = 0;
    if (i < n) g_deg[i] = 1;  // self-loop
    if (blockIdx.x == 0 && threadIdx.x < 32) {
        int lane = threadIdx.x;
        int bad = 0;
        int lim = min(nwords, 4096);
        for (int w = 1 + 2 * lane; w < lim; w += 64)
            if (ei32[w] != 0) bad = 1;
        unsigned any = __ballot_sync(FULLMASK, bad);
        if (lane == 0) g_is64 = any ? 0 : 1;
    }
}

// ---------------- K2: GEMM1 (f32x2) + fused att coeffs + fp16 h1  ||  hist ----------------
__global__ __launch_bounds__(256, 2)
void gemm1_hist_kernel(const float* __restrict__ x, const float* __restrict__ W1,
                       const float* __restrict__ att_src1, const float* __restrict__ att_dst1,
                       const void* __restrict__ ei, int n, int e, int gblocks) {
    if (blockIdx.x >= gblocks) {
        // --------- histogram role ---------
        int is64 = g_is64;
        int tid0 = (blockIdx.x - gblocks) * blockDim.x + threadIdx.x;
        int stride = (gridDim.x - gblocks) * blockDim.x;
        for (int i = tid0; i < e; i += stride) {
            int dst = edge_at(ei, e + i, is64);
            atomicAdd(&g_deg[dst], 1);
        }
        return;
    }
    // --------- GEMM role ---------
    __shared__ float As[16][128];   // [k][m]
    __shared__ float Bs[16][128];   // [k][n]
    __shared__ float sAs[128][4];
    __shared__ float sAd[128][4];
    __shared__ unsigned sMax[4];
    int tid = threadIdx.x;
    int tx = tid & 15;
    int ty = tid >> 4;
    int row0 = blockIdx.x * 128;

    // zero reduction buffers (ordered by first __syncthreads in k-loop)
    ((float*)sAs)[tid * 2]     = 0.f;
    ((float*)sAs)[tid * 2 + 1] = 0.f;
    ((float*)sAd)[tid * 2]     = 0.f;
    ((float*)sAd)[tid * 2 + 1] = 0.f;
    if (tid < 4) sMax[tid] = 0;

    unsigned long long acc2[2][4][2][2];
    #pragma unroll
    for (int rh = 0; rh < 2; rh++)
        #pragma unroll
        for (int r = 0; r < 4; r++)
            #pragma unroll
            for (int ch = 0; ch < 2; ch++) {
                acc2[rh][r][ch][0] = 0ull;
                acc2[rh][r][ch][1] = 0ull;
            }

    for (int kk = 0; kk < 8; kk++) {
        #pragma unroll
        for (int i = 0; i < 2; i++) {
            int idx = tid + i * 256;
            int r = idx >> 2, kv = idx & 3;
            int gr = row0 + r;
            float4 v = make_float4(0.f, 0.f, 0.f, 0.f);
            if (gr < n) v = *(const float4*)&x[gr * 128 + kk * 16 + kv * 4];
            As[kv * 4 + 0][r] = v.x;
            As[kv * 4 + 1][r] = v.y;
            As[kv * 4 + 2][r] = v.z;
            As[kv * 4 + 3][r] = v.w;
        }
        #pragma unroll
        for (int i = 0; i < 2; i++) {
            int idx = tid + i * 256;
            int k = idx >> 5, cv = idx & 31;
            *(float4*)&Bs[k][cv * 4] = *(const float4*)&W1[(kk * 16 + k) * 128 + cv * 4];
        }
        __syncthreads();
        #pragma unroll
        for (int k = 0; k < 16; k++) {
            float4 a0 = *(const float4*)&As[k][ty * 4];
            float4 a1 = *(const float4*)&As[k][64 + ty * 4];
            ulonglong2 bp0 = *(const ulonglong2*)&Bs[k][tx * 4];       // (b0,b1),(b2,b3)
            ulonglong2 bp1 = *(const ulonglong2*)&Bs[k][64 + tx * 4];
            unsigned long long ad_[2][4];
            ad_[0][0] = pk2(a0.x, a0.x); ad_[0][1] = pk2(a0.y, a0.y);
            ad_[0][2] = pk2(a0.z, a0.z); ad_[0][3] = pk2(a0.w, a0.w);
            ad_[1][0] = pk2(a1.x, a1.x); ad_[1][1] = pk2(a1.y, a1.y);
            ad_[1][2] = pk2(a1.z, a1.z); ad_[1][3] = pk2(a1.w, a1.w);
            #pragma unroll
            for (int rh = 0; rh < 2; rh++)
                #pragma unroll
                for (int r = 0; r < 4; r++) {
                    fma2(acc2[rh][r][0][0], ad_[rh][r], bp0.x);
                    fma2(acc2[rh][r][0][1], ad_[rh][r], bp0.y);
                    fma2(acc2[rh][r][1][0], ad_[rh][r], bp1.x);
                    fma2(acc2[rh][r][1][1], ad_[rh][r], bp1.y);
                }
        }
        __syncthreads();
    }

    // epilogue: fp16 store + exact fp32 attention partial dots
    float4 vs[2], vd[2];
    vs[0] = *(const float4*)&att_src1[tx * 4];
    vs[1] = *(const float4*)&att_src1[64 + tx * 4];
    vd[0] = *(const float4*)&att_dst1[tx * 4];
    vd[1] = *(const float4*)&att_dst1[64 + tx * 4];
    int hb = tx >> 3;
    #pragma unroll
    for (int rh = 0; rh < 2; rh++) {
        #pragma unroll
        for (int r = 0; r < 4; r++) {
            int row = rh * 64 + ty * 4 + r;
            int gr = row0 + row;
            if (gr >= n) continue;
            #pragma unroll
            for (int ch = 0; ch < 2; ch++) {
                float2 u0 = upk2(acc2[rh][r][ch][0]);
                float2 u1 = upk2(acc2[rh][r][ch][1]);
                __half2 hA = __floats2half2_rn(u0.x, u0.y);
                __half2 hB = __floats2half2_rn(u1.x, u1.y);
                uint2 st;
                st.x = *(unsigned*)&hA;
                st.y = *(unsigned*)&hB;
                *(uint2*)&g_h1h[gr * 128 + ch * 64 + tx * 4] = st;
                float ps = u0.x * vs[ch].x + u0.y * vs[ch].y + u1.x * vs[ch].z + u1.y * vs[ch].w;
                float pd = u0.x * vd[ch].x + u0.y * vd[ch].y + u1.x * vd[ch].z + u1.y * vd[ch].w;
                atomicAdd(&sAs[row][ch * 2 + hb], ps);
                atomicAdd(&sAd[row][ch * 2 + hb], pd);
            }
        }
    }
    __syncthreads();
    if (tid < 128) {
        int gr = row0 + tid;
        if (gr < n) {
            float4 s4 = *(float4*)&sAs[tid][0];
            float4 d4 = *(float4*)&sAd[tid][0];
            *(float4*)&g_as1[gr * 4] = s4;
            *(float4*)&g_ad1[gr * 4] = d4;
            atomicMax(&sMax[0], fenc(s4.x));
            atomicMax(&sMax[1], fenc(s4.y));
            atomicMax(&sMax[2], fenc(s4.z));
            atomicMax(&sMax[3], fenc(s4.w));
        }
    }
    __syncthreads();
    if (tid < 4) atomicMax(&g_maxenc1[tid], sMax[tid]);
}

// ---------------- offsets: warp-scan + one atomic per warp ----------------
__global__ void offsets_kernel(int n) {
    int i = blockIdx.x * blockDim.x + threadIdx.x;
    int lane = threadIdx.x & 31;
    int d = (i < n) ? g_deg[i] : 0;
    int incl = d;
    #pragma unroll
    for (int o = 1; o < 32; o <<= 1) {
        int v = __shfl_up_sync(FULLMASK, incl, o);
        if (lane >= o) incl += v;
    }
    int wtot = __shfl_sync(FULLMASK, incl, 31);
    int base = 0;
    if (lane == 31) base = atomicAdd(&g_total, wtot);
    base = __shfl_sync(FULLMASK, base, 31);
    if (i < n) {
        int st = base + incl - d;
        g_off[i] = st;
        g_cur[i] = st;
    }
}

__global__ void scatter_kernel(const void* __restrict__ ei, int e, int n) {
    int i = blockIdx.x * blockDim.x + threadIdx.x;
    int is64 = g_is64;
    if (i < e) {
        int dst = edge_at(ei, e + i, is64);
        int src = edge_at(ei, i, is64);
        int pos = atomicAdd(&g_cur[dst], 1);
        g_src[pos] = src;
    } else if (i < e + n) {
        int v = i - e;
        int pos = atomicAdd(&g_cur[v], 1);
        g_src[pos] = v;
    }
}

// ---------------- layer-1 aggregation: warp per node, head-per-lane-group ----------------
__global__ void aggr1_kernel(const float* __restrict__ b1, int n) {
    int node = (blockIdx.x * blockDim.x + threadIdx.x) >> 5;
    int lane = threadIdx.x & 31;
    if (node >= n) return;
    int h = lane >> 3;        // this lane's head
    int cb = lane * 4;        // this lane's 4 columns
    int start = g_off[node];
    int deg = g_deg[node];
    float adh = g_ad1[node * 4 + h];
    float Mh = lrelu(fdec(g_maxenc1[h]) + adh);   // upper-bound shift, softmax-invariant

    float4 acc = make_float4(0.f, 0.f, 0.f, 0.f);
    float ss = 0.f;
    for (int b0 = 0; b0 < deg; b0 += 32) {
        int cnt = min(32, deg - b0);
        int sreg[4]; float ereg[4];
        #pragma unroll
        for (int k2 = 0; k2 < 4; k2++) {
            int jloc = (lane & 7) + 8 * k2;
            sreg[k2] = 0; ereg[k2] = 0.f;
            if (jloc < cnt) {
                int sk = __ldg(&g_src[start + b0 + jloc]);
                sreg[k2] = sk;
                float asv = __ldg(&g_as1[sk * 4 + h]);
                ereg[k2] = __expf(lrelu(asv + adh) - Mh);
            }
        }
        #pragma unroll
        for (int k2 = 0; k2 < 4; k2++) {
            if (k2 * 8 < cnt) {
                #pragma unroll
                for (int jo = 0; jo < 8; jo++) {
                    int j = k2 * 8 + jo;
                    if (j < cnt) {
                        int srcl = (lane & 24) | jo;   // fetch from own head group
                        int sj  = __shfl_sync(FULLMASK, sreg[k2], srcl);
                        float f = __shfl_sync(FULLMASK, ereg[k2], srcl);
                        uint2 hv = __ldg((const uint2*)(g_h1h + sj * 128 + cb));
                        float2 p0 = __half22float2(*(__half2*)&hv.x);
                        float2 p1 = __half22float2(*(__half2*)&hv.y);
                        acc.x = fmaf(f, p0.x, acc.x);
                        acc.y = fmaf(f, p0.y, acc.y);
                        acc.z = fmaf(f, p1.x, acc.z);
                        acc.w = fmaf(f, p1.y, acc.w);
                        ss += f;
                    }
                }
            }
        }
    }
    float4 bb = *(const float4*)&b1[cb];
    float r = 1.0f / (ss + EPS);
    float o0 = acc.x * r + bb.x;
    float o1 = acc.y * r + bb.y;
    float o2 = acc.z * r + bb.z;
    float o3 = acc.w * r + bb.w;
    o0 = o0 > 0.f ? o0 : (__expf(o0) - 1.0f);
    o1 = o1 > 0.f ? o1 : (__expf(o1) - 1.0f);
    o2 = o2 > 0.f ? o2 : (__expf(o2) - 1.0f);
    o3 = o3 > 0.f ? o3 : (__expf(o3) - 1.0f);
    float4 o = make_float4(o0, o1, o2, o3);
    *(float4*)&g_out1[node * 128 + cb] = o;
}

// ---------------- layer 2: GEMM (128->2) + attention coefficients (+ max) ----------------
__global__ void gemm2att_kernel(const float* __restrict__ W2,
                                const float* __restrict__ att_src2,
                                const float* __restrict__ att_dst2, int n) {
    __shared__ unsigned sm;
    if (threadIdx.x == 0) sm = 0;
    __syncthreads();
    int node = (blockIdx.x * blockDim.x + threadIdx.x) >> 5;
    int lane = threadIdx.x & 31;
    if (node < n) {
        float4 v  = *(const float4*)&g_out1[node * 128 + lane * 4];
        float4 w0 = *(const float4*)&W2[lane * 8];
        float4 w1 = *(const float4*)&W2[lane * 8 + 4];
        float a0 = v.x * w0.x + v.y * w0.z + v.z * w1.x + v.w * w1.z;
        float a1 = v.x * w0.y + v.y * w0.w + v.z * w1.y + v.w * w1.w;
        a0 = warp_sum(a0);
        a1 = warp_sum(a1);
        if (lane == 0) {
            g_h2[node * 2 + 0] = a0;
            g_h2[node * 2 + 1] = a1;
            float as2 = a0 * att_src2[0] + a1 * att_src2[1];
            g_as2[node] = as2;
            g_ad2[node] = a0 * att_dst2[0] + a1 * att_dst2[1];
            atomicMax(&sm, fenc(as2));
        }
    }
    __syncthreads();
    if (threadIdx.x == 0) atomicMax(&g_maxenc2, sm);
}

// ---------------- layer-2 aggregation + bias + log_softmax ----------------
__global__ void aggr2_kernel(const float* __restrict__ b2,
                             float* __restrict__ out, int n) {
    int node = (blockIdx.x * blockDim.x + threadIdx.x) >> 5;
    int lane = threadIdx.x & 31;
    if (node >= n) return;
    int start = g_off[node], end = start + g_deg[node];
    float ad = g_ad2[node];
    float M = lrelu(fdec(g_maxenc2) + ad);

    float sum = 0.f, acc0 = 0.f, acc1 = 0.f;
    for (int i = start + lane; i < end; i += 32) {
        int s = __ldg(&g_src[i]);
        float ex = __expf(lrelu(g_as2[s] + ad) - M);
        sum += ex;
        float2 hv = *(const float2*)&g_h2[s * 2];
        acc0 = fmaf(ex, hv.x, acc0);
        acc1 = fmaf(ex, hv.y, acc1);
    }
    sum = warp_sum(sum);
    acc0 = warp_sum(acc0);
    acc1 = warp_sum(acc1);

    if (lane == 0) {
        float o0 = acc0 / (sum + EPS) + b2[0];
        float o1 = acc1 / (sum + EPS) + b2[1];
        float mx = fmaxf(o0, o1);
        float lse = mx + __logf(__expf(o0 - mx) + __expf(o1 - mx));
        out[node * 2 + 0] = o0 - lse;
        out[node * 2 + 1] = o1 - lse;
    }
}

// ---------------- launch ----------------
extern "C" void kernel_launch(void* const* d_in, const int* in_sizes, int n_in,
                              void* d_out, int out_size) {
    const float* x         = (const float*)d_in[0];
    const void*  ei        = (const void*)d_in[1];
    const float* W1        = (const float*)d_in[2];
    const float* att_src1  = (const float*)d_in[3];
    const float* att_dst1  = (const float*)d_in[4];
    const float* b1        = (const float*)d_in[5];
    const float* W2        = (const float*)d_in[6];
    const float* att_src2  = (const float*)d_in[7];
    const float* att_dst2  = (const float*)d_in[8];
    const float* b2        = (const float*)d_in[9];
    float* out             = (float*)d_out;

    int n = in_sizes[0] / 128;   // 50000
    int e = in_sizes[1] / 2;     // 800000

    int gblocks = (n + 127) / 128;   // 391
    int hblocks = 512;

    init_sniff_kernel<<<(n + 255) / 256, 256>>>((const int*)ei, in_sizes[1], n);
    gemm1_hist_kernel<<<gblocks + hblocks, 256>>>(x, W1, att_src1, att_dst1, ei, n, e, gblocks);
    offsets_kernel<<<(n + 255) / 256, 256>>>(n);
    scatter_kernel<<<(e + n + 255) / 256, 256>>>(ei, e, n);
    aggr1_kernel<<<(n * 32 + 255) / 256, 256>>>(b1, n);
    gemm2att_kernel<<<(n * 32 + 255) / 256, 256>>>(W2, att_src2, att_dst2, n);
    aggr2_kernel<<<(n * 32 + 255) / 256, 256>>>(b2, out, n);
}

// round 9
// speedup vs baseline: 1.9430x; 1.0587x over previous
#include <cuda_runtime.h>
#include <cuda_fp16.h>
#include <math.h>

#define NN 50000
#define EE 800000
#define ETOT (EE + NN)
#define NEG_SLOPE 0.2f
#define EPS 1e-16f
#define FULLMASK 0xFFFFFFFFu

// ---------------- scratch (static device globals; no allocation) ----------------
__device__ __align__(16) __half g_h1h[NN * 128];   // layer1 features, fp16 (gather payload)
__device__ __align__(16) float g_as1[NN * 4];      // a_src layer1 (exact fp32)
__device__ __align__(16) float g_ad1[NN * 4];      // a_dst layer1
__device__ __align__(16) float4 g_pk2[NN];         // {h2.x, h2.y, a_src2, a_dst2}
__device__ int g_deg[NN];
__device__ int g_off[NN];
__device__ int g_cur[NN];
__device__ int g_src[ETOT];
__device__ int g_is64;
__device__ int g_total;
__device__ unsigned g_maxenc1[4];   // encoded global max of a_src per head (layer1)
__device__ unsigned g_maxenc2;

// ---------------- helpers ----------------
__device__ __forceinline__ float lrelu(float x) {
    return x > 0.0f ? x : NEG_SLOPE * x;
}
__device__ __forceinline__ float warp_sum(float v) {
    #pragma unroll
    for (int o = 16; o; o >>= 1) v += __shfl_xor_sync(FULLMASK, v, o);
    return v;
}
// order-preserving float<->uint encoding for atomicMax
__device__ __forceinline__ unsigned fenc(float f) {
    unsigned b = __float_as_uint(f);
    return (b & 0x80000000u) ? ~b : (b | 0x80000000u);
}
__device__ __forceinline__ float fdec(unsigned u) {
    return (u & 0x80000000u) ? __uint_as_float(u ^ 0x80000000u)
                             : __uint_as_float(~u);
}
__device__ __forceinline__ int edge_at(const void* ei, int idx, int is64) {
    if (is64) return (int)((const long long*)ei)[idx];
    return ((const int*)ei)[idx];
}
// packed fp32x2 FMA (Blackwell)
__device__ __forceinline__ unsigned long long pk2f(float lo, float hi) {
    unsigned long long r;
    asm("mov.b64 %0, {%1, %2};" : "=l"(r)
        : "r"(__float_as_uint(lo)), "r"(__float_as_uint(hi)));
    return r;
}
__device__ __forceinline__ float2 upk2f(unsigned long long v) {
    unsigned lo, hi;
    asm("mov.b64 {%0, %1}, %2;" : "=r"(lo), "=r"(hi) : "l"(v));
    return make_float2(__uint_as_float(lo), __uint_as_float(hi));
}
__device__ __forceinline__ void fma2(unsigned long long& d,
                                     unsigned long long a, unsigned long long b) {
    asm("fma.rn.f32x2 %0, %1, %2, %0;" : "+l"(d) : "l"(a), "l"(b));
}

// ---------------- K1: init + dtype sniff ----------------
__global__ void init_sniff_kernel(const int* __restrict__ ei32, int nwords, int n) {
    int i = blockIdx.x * blockDim.x + threadIdx.x;
    if (i == 0) g_total = 0;
    if (i < 4) g_maxenc1[i] = 0;
    if (i == 5) g_maxenc2 = 0;
    if (i < n) g_deg[i] = 1;  // self-loop
    if (blockIdx.x == 0 && threadIdx.x < 32) {
        int lane = threadIdx.x;
        int bad = 0;
        int lim = min(nwords, 4096);
        for (int w = 1 + 2 * lane; w < lim; w += 64)
            if (ei32[w] != 0) bad = 1;
        unsigned any = __ballot_sync(FULLMASK, bad);
        if (lane == 0) g_is64 = any ? 0 : 1;
    }
}

// ---------------- K2: GEMM1 (f32x2) + fused att coeffs + fp16 h1  ||  hist ----------------
__global__ __launch_bounds__(256, 2)
void gemm1_hist_kernel(const float* __restrict__ x, const float* __restrict__ W1,
                       const float* __restrict__ att_src1, const float* __restrict__ att_dst1,
                       const void* __restrict__ ei, int n, int e, int gblocks) {
    if (blockIdx.x >= gblocks) {
        // --------- histogram role ---------
        int is64 = g_is64;
        int tid0 = (blockIdx.x - gblocks) * blockDim.x + threadIdx.x;
        int stride = (gridDim.x - gblocks) * blockDim.x;
        for (int i = tid0; i < e; i += stride) {
            int dst = edge_at(ei, e + i, is64);
            atomicAdd(&g_deg[dst], 1);
        }
        return;
    }
    // --------- GEMM role ---------
    __shared__ float As[16][128];   // [k][m]
    __shared__ float Bs[16][128];   // [k][n]
    __shared__ float sAs[128][4];
    __shared__ float sAd[128][4];
    __shared__ unsigned sMax[4];
    int tid = threadIdx.x;
    int tx = tid & 15;
    int ty = tid >> 4;
    int row0 = blockIdx.x * 128;

    ((float*)sAs)[tid * 2]     = 0.f;
    ((float*)sAs)[tid * 2 + 1] = 0.f;
    ((float*)sAd)[tid * 2]     = 0.f;
    ((float*)sAd)[tid * 2 + 1] = 0.f;
    if (tid < 4) sMax[tid] = 0;

    unsigned long long acc2[2][4][2][2];
    #pragma unroll
    for (int rh = 0; rh < 2; rh++)
        #pragma unroll
        for (int r = 0; r < 4; r++)
            #pragma unroll
            for (int ch = 0; ch < 2; ch++) {
                acc2[rh][r][ch][0] = 0ull;
                acc2[rh][r][ch][1] = 0ull;
            }

    for (int kk = 0; kk < 8; kk++) {
        #pragma unroll
        for (int i = 0; i < 2; i++) {
            int idx = tid + i * 256;
            int r = idx >> 2, kv = idx & 3;
            int gr = row0 + r;
            float4 v = make_float4(0.f, 0.f, 0.f, 0.f);
            if (gr < n) v = *(const float4*)&x[gr * 128 + kk * 16 + kv * 4];
            As[kv * 4 + 0][r] = v.x;
            As[kv * 4 + 1][r] = v.y;
            As[kv * 4 + 2][r] = v.z;
            As[kv * 4 + 3][r] = v.w;
        }
        #pragma unroll
        for (int i = 0; i < 2; i++) {
            int idx = tid + i * 256;
            int k = idx >> 5, cv = idx & 31;
            *(float4*)&Bs[k][cv * 4] = *(const float4*)&W1[(kk * 16 + k) * 128 + cv * 4];
        }
        __syncthreads();
        #pragma unroll
        for (int k = 0; k < 16; k++) {
            float4 a0 = *(const float4*)&As[k][ty * 4];
            float4 a1 = *(const float4*)&As[k][64 + ty * 4];
            ulonglong2 bp0 = *(const ulonglong2*)&Bs[k][tx * 4];
            ulonglong2 bp1 = *(const ulonglong2*)&Bs[k][64 + tx * 4];
            unsigned long long ad_[2][4];
            ad_[0][0] = pk2f(a0.x, a0.x); ad_[0][1] = pk2f(a0.y, a0.y);
            ad_[0][2] = pk2f(a0.z, a0.z); ad_[0][3] = pk2f(a0.w, a0.w);
            ad_[1][0] = pk2f(a1.x, a1.x); ad_[1][1] = pk2f(a1.y, a1.y);
            ad_[1][2] = pk2f(a1.z, a1.z); ad_[1][3] = pk2f(a1.w, a1.w);
            #pragma unroll
            for (int rh = 0; rh < 2; rh++)
                #pragma unroll
                for (int r = 0; r < 4; r++) {
                    fma2(acc2[rh][r][0][0], ad_[rh][r], bp0.x);
                    fma2(acc2[rh][r][0][1], ad_[rh][r], bp0.y);
                    fma2(acc2[rh][r][1][0], ad_[rh][r], bp1.x);
                    fma2(acc2[rh][r][1][1], ad_[rh][r], bp1.y);
                }
        }
        __syncthreads();
    }

    // epilogue: fp16 store + exact fp32 attention partial dots
    float4 vs[2], vd[2];
    vs[0] = *(const float4*)&att_src1[tx * 4];
    vs[1] = *(const float4*)&att_src1[64 + tx * 4];
    vd[0] = *(const float4*)&att_dst1[tx * 4];
    vd[1] = *(const float4*)&att_dst1[64 + tx * 4];
    int hb = tx >> 3;
    #pragma unroll
    for (int rh = 0; rh < 2; rh++) {
        #pragma unroll
        for (int r = 0; r < 4; r++) {
            int row = rh * 64 + ty * 4 + r;
            int gr = row0 + row;
            if (gr >= n) continue;
            #pragma unroll
            for (int ch = 0; ch < 2; ch++) {
                float2 u0 = upk2f(acc2[rh][r][ch][0]);
                float2 u1 = upk2f(acc2[rh][r][ch][1]);
                __half2 hA = __floats2half2_rn(u0.x, u0.y);
                __half2 hB = __floats2half2_rn(u1.x, u1.y);
                uint2 st;
                st.x = *(unsigned*)&hA;
                st.y = *(unsigned*)&hB;
                *(uint2*)&g_h1h[gr * 128 + ch * 64 + tx * 4] = st;
                float ps = u0.x * vs[ch].x + u0.y * vs[ch].y + u1.x * vs[ch].z + u1.y * vs[ch].w;
                float pd = u0.x * vd[ch].x + u0.y * vd[ch].y + u1.x * vd[ch].z + u1.y * vd[ch].w;
                atomicAdd(&sAs[row][ch * 2 + hb], ps);
                atomicAdd(&sAd[row][ch * 2 + hb], pd);
            }
        }
    }
    __syncthreads();
    if (tid < 128) {
        int gr = row0 + tid;
        if (gr < n) {
            float4 s4 = *(float4*)&sAs[tid][0];
            float4 d4 = *(float4*)&sAd[tid][0];
            *(float4*)&g_as1[gr * 4] = s4;
            *(float4*)&g_ad1[gr * 4] = d4;
            atomicMax(&sMax[0], fenc(s4.x));
            atomicMax(&sMax[1], fenc(s4.y));
            atomicMax(&sMax[2], fenc(s4.z));
            atomicMax(&sMax[3], fenc(s4.w));
        }
    }
    __syncthreads();
    if (tid < 4) atomicMax(&g_maxenc1[tid], sMax[tid]);
}

// ---------------- offsets: warp-scan + one atomic per warp ----------------
__global__ void offsets_kernel(int n) {
    int i = blockIdx.x * blockDim.x + threadIdx.x;
    int lane = threadIdx.x & 31;
    int d = (i < n) ? g_deg[i] : 0;
    int incl = d;
    #pragma unroll
    for (int o = 1; o < 32; o <<= 1) {
        int v = __shfl_up_sync(FULLMASK, incl, o);
        if (lane >= o) incl += v;
    }
    int wtot = __shfl_sync(FULLMASK, incl, 31);
    int base = 0;
    if (lane == 31) base = atomicAdd(&g_total, wtot);
    base = __shfl_sync(FULLMASK, base, 31);
    if (i < n) {
        int st = base + incl - d;
        g_off[i] = st;
        g_cur[i] = st;
    }
}

// ---------------- scatter: 2 edges per thread (ILP over ATOMG latency) ----------------
__global__ void scatter_kernel(const void* __restrict__ ei, int e, int n) {
    int i = blockIdx.x * blockDim.x + threadIdx.x;
    int is64 = g_is64;
    int half = e >> 1;   // e is even (800000)
    if (i < half) {
        int s0, s1, d0, d1;
        if (is64) {
            const long long* p = (const long long*)ei;
            s0 = (int)p[2 * i];     s1 = (int)p[2 * i + 1];
            d0 = (int)p[e + 2 * i]; d1 = (int)p[e + 2 * i + 1];
        } else {
            int2 sv = ((const int2*)ei)[i];
            int2 dv = ((const int2*)ei)[(e >> 1) + i];
            s0 = sv.x; s1 = sv.y; d0 = dv.x; d1 = dv.y;
        }
        int p0 = atomicAdd(&g_cur[d0], 1);
        int p1 = atomicAdd(&g_cur[d1], 1);
        g_src[p0] = s0;
        g_src[p1] = s1;
    } else if (i < half + n) {
        int v = i - half;
        int pos = atomicAdd(&g_cur[v], 1);
        g_src[pos] = v;  // self loop
    }
}

// ---------------- fused: layer-1 aggregation + ELU + layer-2 GEMM + att2 coeffs ----------------
__global__ __launch_bounds__(256)
void aggr1_fused_kernel(const float* __restrict__ b1, const float* __restrict__ W2,
                        const float* __restrict__ att_src2, const float* __restrict__ att_dst2,
                        int n) {
    __shared__ unsigned sm;
    if (threadIdx.x == 0) sm = 0;
    __syncthreads();
    int node = (blockIdx.x * blockDim.x + threadIdx.x) >> 5;
    int lane = threadIdx.x & 31;
    if (node < n) {
        int h = lane >> 3;        // this lane's head
        int cb = lane * 4;        // this lane's 4 columns
        int start = g_off[node];
        int deg = g_deg[node];
        float adh = g_ad1[node * 4 + h];
        float Mh = lrelu(fdec(g_maxenc1[h]) + adh);   // upper-bound shift

        float4 acc = make_float4(0.f, 0.f, 0.f, 0.f);
        float ss = 0.f;
        for (int b0 = 0; b0 < deg; b0 += 32) {
            int cnt = min(32, deg - b0);
            int sreg[4]; float ereg[4];
            #pragma unroll
            for (int k2 = 0; k2 < 4; k2++) {
                int jloc = (lane & 7) + 8 * k2;
                sreg[k2] = 0; ereg[k2] = 0.f;
                if (jloc < cnt) {
                    int sk = __ldg(&g_src[start + b0 + jloc]);
                    sreg[k2] = sk;
                    float asv = __ldg(&g_as1[sk * 4 + h]);
                    ereg[k2] = __expf(lrelu(asv + adh) - Mh);
                }
            }
            #pragma unroll
            for (int k2 = 0; k2 < 4; k2++) {
                if (k2 * 8 < cnt) {
                    #pragma unroll
                    for (int jo = 0; jo < 8; jo++) {
                        int j = k2 * 8 + jo;
                        if (j < cnt) {
                            int srcl = (lane & 24) | jo;
                            int sj  = __shfl_sync(FULLMASK, sreg[k2], srcl);
                            float f = __shfl_sync(FULLMASK, ereg[k2], srcl);
                            uint2 hv = __ldg((const uint2*)(g_h1h + sj * 128 + cb));
                            float2 p0 = __half22float2(*(__half2*)&hv.x);
                            float2 p1 = __half22float2(*(__half2*)&hv.y);
                            acc.x = fmaf(f, p0.x, acc.x);
                            acc.y = fmaf(f, p0.y, acc.y);
                            acc.z = fmaf(f, p1.x, acc.z);
                            acc.w = fmaf(f, p1.y, acc.w);
                            ss += f;
                        }
                    }
                }
            }
        }
        float4 bb = *(const float4*)&b1[cb];
        float r = 1.0f / (ss + EPS);
        float o0 = acc.x * r + bb.x;
        float o1 = acc.y * r + bb.y;
        float o2 = acc.z * r + bb.z;
        float o3 = acc.w * r + bb.w;
        o0 = o0 > 0.f ? o0 : (__expf(o0) - 1.0f);
        o1 = o1 > 0.f ? o1 : (__expf(o1) - 1.0f);
        o2 = o2 > 0.f ? o2 : (__expf(o2) - 1.0f);
        o3 = o3 > 0.f ? o3 : (__expf(o3) - 1.0f);

        // ---- fused layer-2 projection (out1 never leaves registers) ----
        float4 w0 = *(const float4*)&W2[cb * 2];       // {k0c0,k0c1,k1c0,k1c1}
        float4 w1 = *(const float4*)&W2[cb * 2 + 4];   // {k2c0,k2c1,k3c0,k3c1}
        float a0 = o0 * w0.x + o1 * w0.z + o2 * w1.x + o3 * w1.z;
        float a1 = o0 * w0.y + o1 * w0.w + o2 * w1.y + o3 * w1.w;
        a0 = warp_sum(a0);
        a1 = warp_sum(a1);
        if (lane == 0) {
            float as2 = a0 * att_src2[0] + a1 * att_src2[1];
            float ad2 = a0 * att_dst2[0] + a1 * att_dst2[1];
            g_pk2[node] = make_float4(a0, a1, as2, ad2);
            atomicMax(&sm, fenc(as2));
        }
    }
    __syncthreads();
    if (threadIdx.x == 0) atomicMax(&g_maxenc2, sm);
}

// ---------------- layer-2 aggregation + bias + log_softmax ----------------
__global__ void aggr2_kernel(const float* __restrict__ b2,
                             float* __restrict__ out, int n) {
    int node = (blockIdx.x * blockDim.x + threadIdx.x) >> 5;
    int lane = threadIdx.x & 31;
    if (node >= n) return;
    int start = g_off[node], end = start + g_deg[node];
    float ad = __ldg(&g_pk2[node]).w;
    float M = lrelu(fdec(g_maxenc2) + ad);

    float sum = 0.f, acc0 = 0.f, acc1 = 0.f;
    for (int i = start + lane; i < end; i += 32) {
        int s = __ldg(&g_src[i]);
        float4 p = __ldg(&g_pk2[s]);   // one 16B load per edge
        float ex = __expf(lrelu(p.z + ad) - M);
        sum += ex;
        acc0 = fmaf(ex, p.x, acc0);
        acc1 = fmaf(ex, p.y, acc1);
    }
    sum = warp_sum(sum);
    acc0 = warp_sum(acc0);
    acc1 = warp_sum(acc1);

    if (lane == 0) {
        float o0 = acc0 / (sum + EPS) + b2[0];
        float o1 = acc1 / (sum + EPS) + b2[1];
        float mx = fmaxf(o0, o1);
        float lse = mx + __logf(__expf(o0 - mx) + __expf(o1 - mx));
        out[node * 2 + 0] = o0 - lse;
        out[node * 2 + 1] = o1 - lse;
    }
}

// ---------------- launch ----------------
extern "C" void kernel_launch(void* const* d_in, const int* in_sizes, int n_in,
                              void* d_out, int out_size) {
    const float* x         = (const float*)d_in[0];
    const void*  ei        = (const void*)d_in[1];
    const float* W1        = (const float*)d_in[2];
    const float* att_src1  = (const float*)d_in[3];
    const float* att_dst1  = (const float*)d_in[4];
    const float* b1        = (const float*)d_in[5];
    const float* W2        = (const float*)d_in[6];
    const float* att_src2  = (const float*)d_in[7];
    const float* att_dst2  = (const float*)d_in[8];
    const float* b2        = (const float*)d_in[9];
    float* out             = (float*)d_out;

    int n = in_sizes[0] / 128;   // 50000
    int e = in_sizes[1] / 2;     // 800000

    int gblocks = (n + 127) / 128;   // 391
    int hblocks = 512;

    init_sniff_kernel<<<(n + 255) / 256, 256>>>((const int*)ei, in_sizes[1], n);
    gemm1_hist_kernel<<<gblocks + hblocks, 256>>>(x, W1, att_src1, att_dst1, ei, n, e, gblocks);
    offsets_kernel<<<(n + 255) / 256, 256>>>(n);
    scatter_kernel<<<((e >> 1) + n + 255) / 256, 256>>>(ei, e, n);
    aggr1_fused_kernel<<<(n * 32 + 255) / 256, 256>>>(b1, W2, att_src2, att_dst2, n);
    aggr2_kernel<<<(n * 32 + 255) / 256, 256>>>(b2, out, n);
}

// round 11
// speedup vs baseline: 2.3661x; 1.2177x over previous
#include <cuda_runtime.h>
#include <cuda_fp16.h>
#include <math.h>

#define NN 50000
#define EE 800000
#define ETOT (EE + NN)
#define NEG_SLOPE 0.2f
#define EPS 1e-16f
#define FULLMASK 0xFFFFFFFFu

// ---------------- scratch (static device globals; no allocation) ----------------
__device__ __align__(16) __half g_h1h[NN * 128];   // layer1 features, fp16 (gather payload)
__device__ __align__(16) float g_as1[NN * 4];      // a_src layer1 (fp32 from accums)
__device__ __align__(16) float g_ad1[NN * 4];      // a_dst layer1
__device__ __align__(16) float4 g_pk2[NN];         // {h2.x, h2.y, a_src2, a_dst2}
__device__ int g_deg[NN];
__device__ int g_off[NN];
__device__ int g_cur[NN];
__device__ int g_src[ETOT];
__device__ int g_is64;
__device__ int g_total;
__device__ unsigned g_maxenc1[4];
__device__ unsigned g_maxenc2;

// ---------------- helpers ----------------
__device__ __forceinline__ float lrelu(float x) {
    return x > 0.0f ? x : NEG_SLOPE * x;
}
__device__ __forceinline__ float warp_sum(float v) {
    #pragma unroll
    for (int o = 16; o; o >>= 1) v += __shfl_xor_sync(FULLMASK, v, o);
    return v;
}
__device__ __forceinline__ unsigned fenc(float f) {
    unsigned b = __float_as_uint(f);
    return (b & 0x80000000u) ? ~b : (b | 0x80000000u);
}
__device__ __forceinline__ float fdec(unsigned u) {
    return (u & 0x80000000u) ? __uint_as_float(u ^ 0x80000000u)
                             : __uint_as_float(~u);
}
__device__ __forceinline__ int edge_at(const void* ei, int idx, int is64) {
    if (is64) return (int)((const long long*)ei)[idx];
    return ((const int*)ei)[idx];
}
__device__ __forceinline__ unsigned tf32b(float f) {
    unsigned r;
    asm("cvt.rna.tf32.f32 %0, %1;" : "=r"(r) : "f"(f));
    return r;
}
__device__ __forceinline__ void mma_tf32(float* c, const unsigned* a, const unsigned* b) {
    asm("mma.sync.aligned.m16n8k8.row.col.f32.tf32.tf32.f32 "
        "{%0,%1,%2,%3},{%4,%5,%6,%7},{%8,%9},{%0,%1,%2,%3};"
        : "+f"(c[0]), "+f"(c[1]), "+f"(c[2]), "+f"(c[3])
        : "r"(a[0]), "r"(a[1]), "r"(a[2]), "r"(a[3]), "r"(b[0]), "r"(b[1]));
}

// ---------------- K1: init + dtype sniff ----------------
__global__ void init_sniff_kernel(const int* __restrict__ ei32, int nwords, int n) {
    int i = blockIdx.x * blockDim.x + threadIdx.x;
    if (i == 0) g_total = 0;
    if (i < 4) g_maxenc1[i] = 0;
    if (i == 5) g_maxenc2 = 0;
    if (i < n) g_deg[i] = 1;  // self-loop
    if (blockIdx.x == 0 && threadIdx.x < 32) {
        int lane = threadIdx.x;
        int bad = 0;
        int lim = min(nwords, 4096);
        for (int w = 1 + 2 * lane; w < lim; w += 64)
            if (ei32[w] != 0) bad = 1;
        unsigned any = __ballot_sync(FULLMASK, bad);
        if (lane == 0) g_is64 = any ? 0 : 1;
    }
}

// ---------------- K2: GEMM1 (tf32 HMMA) + fused att coeffs + fp16 h1  ||  hist ----------------
__global__ __launch_bounds__(256, 2)
void gemm1_hist_kernel(const float* __restrict__ x, const float* __restrict__ W1,
                       const float* __restrict__ att_src1, const float* __restrict__ att_dst1,
                       const void* __restrict__ ei, int n, int e, int gblocks) {
    if (blockIdx.x >= gblocks) {
        // --------- histogram role ---------
        int is64 = g_is64;
        int tid0 = (blockIdx.x - gblocks) * blockDim.x + threadIdx.x;
        int stride = (gridDim.x - gblocks) * blockDim.x;
        for (int i = tid0; i < e; i += stride) {
            int dst = edge_at(ei, e + i, is64);
            atomicAdd(&g_deg[dst], 1);
        }
        return;
    }
    // --------- GEMM role: 128x128 tile, 8 warps in 4(m) x 2(n), mma m16n8k8 tf32 ---------
    __shared__ unsigned As[16][136];   // [k][m], tf32 bits; bank = (8k+m)%32 conflict-free
    __shared__ unsigned Bs[16][132];   // [k][n], tf32 bits
    __shared__ float sAs[128][4];
    __shared__ float sAd[128][4];
    __shared__ unsigned sMax[4];
    int tid = threadIdx.x;
    int lane = tid & 31;
    int wid = tid >> 5;
    int wm = wid >> 1;                 // 0..3 : rows 32*wm
    int wn = wid & 1;                  // 0..1 : cols 64*wn
    int g = lane >> 2;                 // 0..7
    int tq = lane & 3;                 // 0..3
    int row0 = blockIdx.x * 128;

    ((float*)sAs)[tid * 2]     = 0.f;
    ((float*)sAs)[tid * 2 + 1] = 0.f;
    ((float*)sAd)[tid * 2]     = 0.f;
    ((float*)sAd)[tid * 2 + 1] = 0.f;
    if (tid < 4) sMax[tid] = 0;

    float C[2][8][4];
    #pragma unroll
    for (int mf = 0; mf < 2; mf++)
        #pragma unroll
        for (int nf = 0; nf < 8; nf++)
            #pragma unroll
            for (int q = 0; q < 4; q++) C[mf][nf][q] = 0.f;

    for (int kk = 0; kk < 8; kk++) {
        // stage A: 128 rows x 16 k, transpose to As[k][m] with tf32 cvt
        #pragma unroll
        for (int i = 0; i < 2; i++) {
            int idx = tid + i * 256;
            int r = idx >> 2, kv = idx & 3;
            int gr = row0 + r;
            float4 v = make_float4(0.f, 0.f, 0.f, 0.f);
            if (gr < n) v = *(const float4*)&x[gr * 128 + kk * 16 + kv * 4];
            As[kv * 4 + 0][r] = tf32b(v.x);
            As[kv * 4 + 1][r] = tf32b(v.y);
            As[kv * 4 + 2][r] = tf32b(v.z);
            As[kv * 4 + 3][r] = tf32b(v.w);
        }
        // stage B: 16 k x 128 n with tf32 cvt
        #pragma unroll
        for (int i = 0; i < 2; i++) {
            int idx = tid + i * 256;
            int k = idx >> 5, cv = idx & 31;
            float4 v = *(const float4*)&W1[(kk * 16 + k) * 128 + cv * 4];
            uint4 u;
            u.x = tf32b(v.x); u.y = tf32b(v.y); u.z = tf32b(v.z); u.w = tf32b(v.w);
            *(uint4*)&Bs[k][cv * 4] = u;
        }
        __syncthreads();
        #pragma unroll
        for (int ks = 0; ks < 2; ks++) {
            int k0 = ks * 8;
            unsigned a[2][4];
            #pragma unroll
            for (int mf = 0; mf < 2; mf++) {
                int m0 = wm * 32 + mf * 16;
                a[mf][0] = As[k0 + tq][m0 + g];
                a[mf][1] = As[k0 + tq][m0 + 8 + g];
                a[mf][2] = As[k0 + 4 + tq][m0 + g];
                a[mf][3] = As[k0 + 4 + tq][m0 + 8 + g];
            }
            unsigned b[8][2];
            #pragma unroll
            for (int nf = 0; nf < 8; nf++) {
                int n0 = wn * 64 + nf * 8;
                b[nf][0] = Bs[k0 + tq][n0 + g];
                b[nf][1] = Bs[k0 + 4 + tq][n0 + g];
            }
            #pragma unroll
            for (int mf = 0; mf < 2; mf++)
                #pragma unroll
                for (int nf = 0; nf < 8; nf++)
                    mma_tf32(C[mf][nf], a[mf], b[nf]);
        }
        __syncthreads();
    }

    // epilogue: fp16 store + fp32 attention partial dots from accumulators
    #pragma unroll
    for (int mf = 0; mf < 2; mf++) {
        int rl0 = wm * 32 + mf * 16 + g;   // block-local rows
        int rl1 = rl0 + 8;
        int gr0 = row0 + rl0;
        int gr1 = row0 + rl1;
        #pragma unroll
        for (int grp = 0; grp < 2; grp++) {
            float ps0 = 0.f, pd0 = 0.f, ps1 = 0.f, pd1 = 0.f;
            #pragma unroll
            for (int j = 0; j < 4; j++) {
                int nf = grp * 4 + j;
                int col = wn * 64 + nf * 8 + tq * 2;
                float c0 = C[mf][nf][0], c1 = C[mf][nf][1];
                float c2 = C[mf][nf][2], c3 = C[mf][nf][3];
                if (gr0 < n) *(__half2*)&g_h1h[gr0 * 128 + col] = __floats2half2_rn(c0, c1);
                if (gr1 < n) *(__half2*)&g_h1h[gr1 * 128 + col] = __floats2half2_rn(c2, c3);
                float s0 = __ldg(&att_src1[col]), s1 = __ldg(&att_src1[col + 1]);
                float d0 = __ldg(&att_dst1[col]), d1 = __ldg(&att_dst1[col + 1]);
                ps0 += c0 * s0 + c1 * s1;
                pd0 += c0 * d0 + c1 * d1;
                ps1 += c2 * s0 + c3 * s1;
                pd1 += c2 * d0 + c3 * d1;
            }
            int head = wn * 2 + grp;
            if (gr0 < n) { atomicAdd(&sAs[rl0][head], ps0); atomicAdd(&sAd[rl0][head], pd0); }
            if (gr1 < n) { atomicAdd(&sAs[rl1][head], ps1); atomicAdd(&sAd[rl1][head], pd1); }
        }
    }
    __syncthreads();
    if (tid < 128) {
        int gr = row0 + tid;
        if (gr < n) {
            float4 s4 = *(float4*)&sAs[tid][0];
            float4 d4 = *(float4*)&sAd[tid][0];
            *(float4*)&g_as1[gr * 4] = s4;
            *(float4*)&g_ad1[gr * 4] = d4;
            atomicMax(&sMax[0], fenc(s4.x));
            atomicMax(&sMax[1], fenc(s4.y));
            atomicMax(&sMax[2], fenc(s4.z));
            atomicMax(&sMax[3], fenc(s4.w));
        }
    }
    __syncthreads();
    if (tid < 4) atomicMax(&g_maxenc1[tid], sMax[tid]);
}

// ---------------- offsets: warp-scan + one atomic per warp ----------------
__global__ void offsets_kernel(int n) {
    int i = blockIdx.x * blockDim.x + threadIdx.x;
    int lane = threadIdx.x & 31;
    int d = (i < n) ? g_deg[i] : 0;
    int incl = d;
    #pragma unroll
    for (int o = 1; o < 32; o <<= 1) {
        int v = __shfl_up_sync(FULLMASK, incl, o);
        if (lane >= o) incl += v;
    }
    int wtot = __shfl_sync(FULLMASK, incl, 31);
    int base = 0;
    if (lane == 31) base = atomicAdd(&g_total, wtot);
    base = __shfl_sync(FULLMASK, base, 31);
    if (i < n) {
        int st = base + incl - d;
        g_off[i] = st;
        g_cur[i] = st;
    }
}

// ---------------- scatter ----------------
__global__ void scatter_kernel(const void* __restrict__ ei, int e, int n) {
    int i = blockIdx.x * blockDim.x + threadIdx.x;
    int is64 = g_is64;
    int half = e >> 1;
    if (i < half) {
        int s0, s1, d0, d1;
        if (is64) {
            const long long* p = (const long long*)ei;
            s0 = (int)p[2 * i];     s1 = (int)p[2 * i + 1];
            d0 = (int)p[e + 2 * i]; d1 = (int)p[e + 2 * i + 1];
        } else {
            int2 sv = ((const int2*)ei)[i];
            int2 dv = ((const int2*)ei)[(e >> 1) + i];
            s0 = sv.x; s1 = sv.y; d0 = dv.x; d1 = dv.y;
        }
        int p0 = atomicAdd(&g_cur[d0], 1);
        int p1 = atomicAdd(&g_cur[d1], 1);
        g_src[p0] = s0;
        g_src[p1] = s1;
    } else if (i < half + n) {
        int v = i - half;
        int pos = atomicAdd(&g_cur[v], 1);
        g_src[pos] = v;  // self loop
    }
}

// ---------------- fused: layer-1 aggregation + ELU + layer-2 GEMM + att2 coeffs ----------------
__global__ __launch_bounds__(256)
void aggr1_fused_kernel(const float* __restrict__ b1, const float* __restrict__ W2,
                        const float* __restrict__ att_src2, const float* __restrict__ att_dst2,
                        int n) {
    __shared__ unsigned sm;
    if (threadIdx.x == 0) sm = 0;
    __syncthreads();
    int node = (blockIdx.x * blockDim.x + threadIdx.x) >> 5;
    int lane = threadIdx.x & 31;
    if (node < n) {
        int h = lane >> 3;
        int cb = lane * 4;
        int start = g_off[node];
        int deg = g_deg[node];
        float adh = g_ad1[node * 4 + h];
        float Mh = lrelu(fdec(g_maxenc1[h]) + adh);

        float4 acc = make_float4(0.f, 0.f, 0.f, 0.f);
        float ss = 0.f;
        for (int b0 = 0; b0 < deg; b0 += 32) {
            int cnt = min(32, deg - b0);
            int sreg[4]; float ereg[4];
            #pragma unroll
            for (int k2 = 0; k2 < 4; k2++) {
                int jloc = (lane & 7) + 8 * k2;
                sreg[k2] = 0; ereg[k2] = 0.f;
                if (jloc < cnt) {
                    int sk = __ldg(&g_src[start + b0 + jloc]);
                    sreg[k2] = sk;
                    float asv = __ldg(&g_as1[sk * 4 + h]);
                    ereg[k2] = __expf(lrelu(asv + adh) - Mh);
                }
            }
            #pragma unroll
            for (int k2 = 0; k2 < 4; k2++) {
                if (k2 * 8 < cnt) {
                    #pragma unroll
                    for (int jo = 0; jo < 8; jo++) {
                        int j = k2 * 8 + jo;
                        if (j < cnt) {
                            int srcl = (lane & 24) | jo;
                            int sj  = __shfl_sync(FULLMASK, sreg[k2], srcl);
                            float f = __shfl_sync(FULLMASK, ereg[k2], srcl);
                            uint2 hv = __ldg((const uint2*)(g_h1h + sj * 128 + cb));
                            float2 p0 = __half22float2(*(__half2*)&hv.x);
                            float2 p1 = __half22float2(*(__half2*)&hv.y);
                            acc.x = fmaf(f, p0.x, acc.x);
                            acc.y = fmaf(f, p0.y, acc.y);
                            acc.z = fmaf(f, p1.x, acc.z);
                            acc.w = fmaf(f, p1.y, acc.w);
                            ss += f;
                        }
                    }
                }
            }
        }
        float4 bb = *(const float4*)&b1[cb];
        float r = 1.0f / (ss + EPS);
        float o0 = acc.x * r + bb.x;
        float o1 = acc.y * r + bb.y;
        float o2 = acc.z * r + bb.z;
        float o3 = acc.w * r + bb.w;
        o0 = o0 > 0.f ? o0 : (__expf(o0) - 1.0f);
        o1 = o1 > 0.f ? o1 : (__expf(o1) - 1.0f);
        o2 = o2 > 0.f ? o2 : (__expf(o2) - 1.0f);
        o3 = o3 > 0.f ? o3 : (__expf(o3) - 1.0f);

        float4 w0 = *(const float4*)&W2[cb * 2];
        float4 w1 = *(const float4*)&W2[cb * 2 + 4];
        float a0 = o0 * w0.x + o1 * w0.z + o2 * w1.x + o3 * w1.z;
        float a1 = o0 * w0.y + o1 * w0.w + o2 * w1.y + o3 * w1.w;
        a0 = warp_sum(a0);
        a1 = warp_sum(a1);
        if (lane == 0) {
            float as2 = a0 * att_src2[0] + a1 * att_src2[1];
            float ad2 = a0 * att_dst2[0] + a1 * att_dst2[1];
            g_pk2[node] = make_float4(a0, a1, as2, ad2);
            atomicMax(&sm, fenc(as2));
        }
    }
    __syncthreads();
    if (threadIdx.x == 0) atomicMax(&g_maxenc2, sm);
}

// ---------------- layer-2 aggregation + bias + log_softmax ----------------
__global__ void aggr2_kernel(const float* __restrict__ b2,
                             float* __restrict__ out, int n) {
    int node = (blockIdx.x * blockDim.x + threadIdx.x) >> 5;
    int lane = threadIdx.x & 31;
    if (node >= n) return;
    int start = g_off[node], end = start + g_deg[node];
    float ad = __ldg(&g_pk2[node]).w;
    float M = lrelu(fdec(g_maxenc2) + ad);

    float sum = 0.f, acc0 = 0.f, acc1 = 0.f;
    for (int i = start + lane; i < end; i += 32) {
        int s = __ldg(&g_src[i]);
        float4 p = __ldg(&g_pk2[s]);
        float ex = __expf(lrelu(p.z + ad) - M);
        sum += ex;
        acc0 = fmaf(ex, p.x, acc0);
        acc1 = fmaf(ex, p.y, acc1);
    }
    sum = warp_sum(sum);
    acc0 = warp_sum(acc0);
    acc1 = warp_sum(acc1);

    if (lane == 0) {
        float o0 = acc0 / (sum + EPS) + b2[0];
        float o1 = acc1 / (sum + EPS) + b2[1];
        float mx = fmaxf(o0, o1);
        float lse = mx + __logf(__expf(o0 - mx) + __expf(o1 - mx));
        out[node * 2 + 0] = o0 - lse;
        out[node * 2 + 1] = o1 - lse;
    }
}

// ---------------- launch ----------------
extern "C" void kernel_launch(void* const* d_in, const int* in_sizes, int n_in,
                              void* d_out, int out_size) {
    const float* x         = (const float*)d_in[0];
    const void*  ei        = (const void*)d_in[1];
    const float* W1        = (const float*)d_in[2];
    const float* att_src1  = (const float*)d_in[3];
    const float* att_dst1  = (const float*)d_in[4];
    const float* b1        = (const float*)d_in[5];
    const float* W2        = (const float*)d_in[6];
    const float* att_src2  = (const float*)d_in[7];
    const float* att_dst2  = (const float*)d_in[8];
    const float* b2        = (const float*)d_in[9];
    float* out             = (float*)d_out;

    int n = in_sizes[0] / 128;   // 50000
    int e = in_sizes[1] / 2;     // 800000

    int gblocks = (n + 127) / 128;   // 391
    int hblocks = 512;

    init_sniff_kernel<<<(n + 255) / 256, 256>>>((const int*)ei, in_sizes[1], n);
    gemm1_hist_kernel<<<gblocks + hblocks, 256>>>(x, W1, att_src1, att_dst1, ei, n, e, gblocks);
    offsets_kernel<<<(n + 255) / 256, 256>>>(n);
    scatter_kernel<<<((e >> 1) + n + 255) / 256, 256>>>(ei, e, n);
    aggr1_fused_kernel<<<(n * 32 + 255) / 256, 256>>>(b1, W2, att_src2, att_dst2, n);
    aggr2_kernel<<<(n * 32 + 255) / 256, 256>>>(b2, out, n);
}

// round 12
// speedup vs baseline: 2.4610x; 1.0401x over previous
#include <cuda_runtime.h>
#include <cuda_fp16.h>
#include <math.h>

#define NN 50000
#define EE 800000
#define ETOT (EE + NN)
#define NEG_SLOPE 0.2f
#define EPS 1e-16f
#define FULLMASK 0xFFFFFFFFu

// ---------------- scratch (static device globals; no allocation) ----------------
__device__ __align__(16) __half g_h1h[NN * 128];   // layer1 features, fp16 (gather payload)
__device__ __align__(16) float g_as1[NN * 4];      // a_src layer1
__device__ __align__(16) float g_ad1[NN * 4];      // a_dst layer1
__device__ __align__(16) float4 g_pk2[NN];         // {h2.x, h2.y, a_src2, a_dst2}
__device__ int g_deg[NN];
__device__ int g_off[NN];
__device__ int g_cur[NN];
__device__ int g_src[ETOT];
__device__ int g_is64;
__device__ int g_total;
__device__ unsigned g_maxenc1[4];
__device__ unsigned g_maxenc2;

// ---------------- helpers ----------------
__device__ __forceinline__ float lrelu(float x) {
    return x > 0.0f ? x : NEG_SLOPE * x;
}
__device__ __forceinline__ float warp_sum(float v) {
    #pragma unroll
    for (int o = 16; o; o >>= 1) v += __shfl_xor_sync(FULLMASK, v, o);
    return v;
}
__device__ __forceinline__ unsigned fenc(float f) {
    unsigned b = __float_as_uint(f);
    return (b & 0x80000000u) ? ~b : (b | 0x80000000u);
}
__device__ __forceinline__ float fdec(unsigned u) {
    return (u & 0x80000000u) ? __uint_as_float(u ^ 0x80000000u)
                             : __uint_as_float(~u);
}
__device__ __forceinline__ int edge_at(const void* ei, int idx, int is64) {
    if (is64) return (int)((const long long*)ei)[idx];
    return ((const int*)ei)[idx];
}
__device__ __forceinline__ unsigned tf32b(float f) {
    unsigned r;
    asm("cvt.rna.tf32.f32 %0, %1;" : "=r"(r) : "f"(f));
    return r;
}
__device__ __forceinline__ void mma_tf32(float* c, const unsigned* a, const unsigned* b) {
    asm("mma.sync.aligned.m16n8k8.row.col.f32.tf32.tf32.f32 "
        "{%0,%1,%2,%3},{%4,%5,%6,%7},{%8,%9},{%0,%1,%2,%3};"
        : "+f"(c[0]), "+f"(c[1]), "+f"(c[2]), "+f"(c[3])
        : "r"(a[0]), "r"(a[1]), "r"(a[2]), "r"(a[3]), "r"(b[0]), "r"(b[1]));
}

// ---------------- K1: init + dtype sniff ----------------
__global__ void init_sniff_kernel(const int* __restrict__ ei32, int nwords, int n) {
    int i = blockIdx.x * blockDim.x + threadIdx.x;
    if (i == 0) g_total = 0;
    if (i < 4) g_maxenc1[i] = 0;
    if (i == 5) g_maxenc2 = 0;
    if (i < n) g_deg[i] = 1;  // self-loop
    if (blockIdx.x == 0 && threadIdx.x < 32) {
        int lane = threadIdx.x;
        int bad = 0;
        int lim = min(nwords, 4096);
        for (int w = 1 + 2 * lane; w < lim; w += 64)
            if (ei32[w] != 0) bad = 1;
        unsigned any = __ballot_sync(FULLMASK, bad);
        if (lane == 0) g_is64 = any ? 0 : 1;
    }
}

// ---------------- hist (standalone, overlapped with gemm1 on another stream) ----------------
__global__ void hist_kernel(const void* __restrict__ ei, int e) {
    int is64 = g_is64;
    int tid0 = blockIdx.x * blockDim.x + threadIdx.x;
    int stride = gridDim.x * blockDim.x;
    for (int i = tid0; i < e; i += stride) {
        int dst = edge_at(ei, e + i, is64);
        atomicAdd(&g_deg[dst], 1);
    }
}

// ---------------- GEMM1 (tf32 HMMA) + fused att coeffs + fp16 h1 ----------------
__global__ __launch_bounds__(256, 2)
void gemm1_kernel(const float* __restrict__ x, const float* __restrict__ W1,
                  const float* __restrict__ att_src1, const float* __restrict__ att_dst1,
                  int n) {
    // 128x128 tile, 8 warps in 4(m) x 2(n), mma m16n8k8 tf32
    __shared__ unsigned As[16][136];   // [k][m]; bank = (8k+m)%32 conflict-free
    __shared__ unsigned Bs[16][132];   // [k][n]
    __shared__ float sAs[128][4];
    __shared__ float sAd[128][4];
    __shared__ unsigned sMax[4];
    int tid = threadIdx.x;
    int lane = tid & 31;
    int wid = tid >> 5;
    int wm = wid >> 1;
    int wn = wid & 1;
    int g = lane >> 2;
    int tq = lane & 3;
    int row0 = blockIdx.x * 128;

    ((float*)sAs)[tid * 2]     = 0.f;
    ((float*)sAs)[tid * 2 + 1] = 0.f;
    ((float*)sAd)[tid * 2]     = 0.f;
    ((float*)sAd)[tid * 2 + 1] = 0.f;
    if (tid < 4) sMax[tid] = 0;

    float C[2][8][4];
    #pragma unroll
    for (int mf = 0; mf < 2; mf++)
        #pragma unroll
        for (int nf = 0; nf < 8; nf++)
            #pragma unroll
            for (int q = 0; q < 4; q++) C[mf][nf][q] = 0.f;

    for (int kk = 0; kk < 8; kk++) {
        #pragma unroll
        for (int i = 0; i < 2; i++) {
            int idx = tid + i * 256;
            int r = idx >> 2, kv = idx & 3;
            int gr = row0 + r;
            float4 v = make_float4(0.f, 0.f, 0.f, 0.f);
            if (gr < n) v = *(const float4*)&x[gr * 128 + kk * 16 + kv * 4];
            As[kv * 4 + 0][r] = tf32b(v.x);
            As[kv * 4 + 1][r] = tf32b(v.y);
            As[kv * 4 + 2][r] = tf32b(v.z);
            As[kv * 4 + 3][r] = tf32b(v.w);
        }
        #pragma unroll
        for (int i = 0; i < 2; i++) {
            int idx = tid + i * 256;
            int k = idx >> 5, cv = idx & 31;
            float4 v = *(const float4*)&W1[(kk * 16 + k) * 128 + cv * 4];
            uint4 u;
            u.x = tf32b(v.x); u.y = tf32b(v.y); u.z = tf32b(v.z); u.w = tf32b(v.w);
            *(uint4*)&Bs[k][cv * 4] = u;
        }
        __syncthreads();
        #pragma unroll
        for (int ks = 0; ks < 2; ks++) {
            int k0 = ks * 8;
            unsigned a[2][4];
            #pragma unroll
            for (int mf = 0; mf < 2; mf++) {
                int m0 = wm * 32 + mf * 16;
                a[mf][0] = As[k0 + tq][m0 + g];
                a[mf][1] = As[k0 + tq][m0 + 8 + g];
                a[mf][2] = As[k0 + 4 + tq][m0 + g];
                a[mf][3] = As[k0 + 4 + tq][m0 + 8 + g];
            }
            unsigned b[8][2];
            #pragma unroll
            for (int nf = 0; nf < 8; nf++) {
                int n0 = wn * 64 + nf * 8;
                b[nf][0] = Bs[k0 + tq][n0 + g];
                b[nf][1] = Bs[k0 + 4 + tq][n0 + g];
            }
            #pragma unroll
            for (int mf = 0; mf < 2; mf++)
                #pragma unroll
                for (int nf = 0; nf < 8; nf++)
                    mma_tf32(C[mf][nf], a[mf], b[nf]);
        }
        __syncthreads();
    }

    // epilogue: fp16 store + fp32 attention partial dots
    #pragma unroll
    for (int mf = 0; mf < 2; mf++) {
        int rl0 = wm * 32 + mf * 16 + g;
        int rl1 = rl0 + 8;
        int gr0 = row0 + rl0;
        int gr1 = row0 + rl1;
        #pragma unroll
        for (int grp = 0; grp < 2; grp++) {
            float ps0 = 0.f, pd0 = 0.f, ps1 = 0.f, pd1 = 0.f;
            #pragma unroll
            for (int j = 0; j < 4; j++) {
                int nf = grp * 4 + j;
                int col = wn * 64 + nf * 8 + tq * 2;
                float c0 = C[mf][nf][0], c1 = C[mf][nf][1];
                float c2 = C[mf][nf][2], c3 = C[mf][nf][3];
                if (gr0 < n) *(__half2*)&g_h1h[gr0 * 128 + col] = __floats2half2_rn(c0, c1);
                if (gr1 < n) *(__half2*)&g_h1h[gr1 * 128 + col] = __floats2half2_rn(c2, c3);
                float s0 = __ldg(&att_src1[col]), s1 = __ldg(&att_src1[col + 1]);
                float d0 = __ldg(&att_dst1[col]), d1 = __ldg(&att_dst1[col + 1]);
                ps0 += c0 * s0 + c1 * s1;
                pd0 += c0 * d0 + c1 * d1;
                ps1 += c2 * s0 + c3 * s1;
                pd1 += c2 * d0 + c3 * d1;
            }
            int head = wn * 2 + grp;
            if (gr0 < n) { atomicAdd(&sAs[rl0][head], ps0); atomicAdd(&sAd[rl0][head], pd0); }
            if (gr1 < n) { atomicAdd(&sAs[rl1][head], ps1); atomicAdd(&sAd[rl1][head], pd1); }
        }
    }
    __syncthreads();
    if (tid < 128) {
        int gr = row0 + tid;
        if (gr < n) {
            float4 s4 = *(float4*)&sAs[tid][0];
            float4 d4 = *(float4*)&sAd[tid][0];
            *(float4*)&g_as1[gr * 4] = s4;
            *(float4*)&g_ad1[gr * 4] = d4;
            atomicMax(&sMax[0], fenc(s4.x));
            atomicMax(&sMax[1], fenc(s4.y));
            atomicMax(&sMax[2], fenc(s4.z));
            atomicMax(&sMax[3], fenc(s4.w));
        }
    }
    __syncthreads();
    if (tid < 4) atomicMax(&g_maxenc1[tid], sMax[tid]);
}

// ---------------- offsets: warp-scan + one atomic per warp ----------------
__global__ void offsets_kernel(int n) {
    int i = blockIdx.x * blockDim.x + threadIdx.x;
    int lane = threadIdx.x & 31;
    int d = (i < n) ? g_deg[i] : 0;
    int incl = d;
    #pragma unroll
    for (int o = 1; o < 32; o <<= 1) {
        int v = __shfl_up_sync(FULLMASK, incl, o);
        if (lane >= o) incl += v;
    }
    int wtot = __shfl_sync(FULLMASK, incl, 31);
    int base = 0;
    if (lane == 31) base = atomicAdd(&g_total, wtot);
    base = __shfl_sync(FULLMASK, base, 31);
    if (i < n) {
        int st = base + incl - d;
        g_off[i] = st;
        g_cur[i] = st;
    }
}

// ---------------- scatter ----------------
__global__ void scatter_kernel(const void* __restrict__ ei, int e, int n) {
    int i = blockIdx.x * blockDim.x + threadIdx.x;
    int is64 = g_is64;
    int half = e >> 1;
    if (i < half) {
        int s0, s1, d0, d1;
        if (is64) {
            const long long* p = (const long long*)ei;
            s0 = (int)p[2 * i];     s1 = (int)p[2 * i + 1];
            d0 = (int)p[e + 2 * i]; d1 = (int)p[e + 2 * i + 1];
        } else {
            int2 sv = ((const int2*)ei)[i];
            int2 dv = ((const int2*)ei)[(e >> 1) + i];
            s0 = sv.x; s1 = sv.y; d0 = dv.x; d1 = dv.y;
        }
        int p0 = atomicAdd(&g_cur[d0], 1);
        int p1 = atomicAdd(&g_cur[d1], 1);
        g_src[p0] = s0;
        g_src[p1] = s1;
    } else if (i < half + n) {
        int v = i - half;
        int pos = atomicAdd(&g_cur[v], 1);
        g_src[pos] = v;  // self loop
    }
}

// ---------------- fused: layer-1 aggregation + ELU + layer-2 GEMM + att2 coeffs ----------------
__global__ __launch_bounds__(256)
void aggr1_fused_kernel(const float* __restrict__ b1, const float* __restrict__ W2,
                        const float* __restrict__ att_src2, const float* __restrict__ att_dst2,
                        int n) {
    __shared__ unsigned sm;
    if (threadIdx.x == 0) sm = 0;
    __syncthreads();
    int node = (blockIdx.x * blockDim.x + threadIdx.x) >> 5;
    int lane = threadIdx.x & 31;
    if (node < n) {
        int h = lane >> 3;
        int cb = lane * 4;
        int start = g_off[node];
        int deg = g_deg[node];
        float adh = g_ad1[node * 4 + h];
        float Mh = lrelu(fdec(g_maxenc1[h]) + adh);

        float4 acc = make_float4(0.f, 0.f, 0.f, 0.f);
        float ss = 0.f;
        for (int b0 = 0; b0 < deg; b0 += 32) {
            int cnt = min(32, deg - b0);
            int sreg[4]; float ereg[4];
            #pragma unroll
            for (int k2 = 0; k2 < 4; k2++) {
                int jloc = (lane & 7) + 8 * k2;
                sreg[k2] = 0; ereg[k2] = 0.f;
                if (jloc < cnt) {
                    int sk = __ldg(&g_src[start + b0 + jloc]);
                    sreg[k2] = sk;
                    float asv = __ldg(&g_as1[sk * 4 + h]);
                    ereg[k2] = __expf(lrelu(asv + adh) - Mh);
                }
            }
            #pragma unroll
            for (int k2 = 0; k2 < 4; k2++) {
                if (k2 * 8 < cnt) {
                    #pragma unroll
                    for (int jo = 0; jo < 8; jo++) {
                        int j = k2 * 8 + jo;
                        if (j < cnt) {
                            int srcl = (lane & 24) | jo;
                            int sj  = __shfl_sync(FULLMASK, sreg[k2], srcl);
                            float f = __shfl_sync(FULLMASK, ereg[k2], srcl);
                            uint2 hv = __ldg((const uint2*)(g_h1h + sj * 128 + cb));
                            float2 p0 = __half22float2(*(__half2*)&hv.x);
                            float2 p1 = __half22float2(*(__half2*)&hv.y);
                            acc.x = fmaf(f, p0.x, acc.x);
                            acc.y = fmaf(f, p0.y, acc.y);
                            acc.z = fmaf(f, p1.x, acc.z);
                            acc.w = fmaf(f, p1.y, acc.w);
                            ss += f;
                        }
                    }
                }
            }
        }
        float4 bb = *(const float4*)&b1[cb];
        float r = 1.0f / (ss + EPS);
        float o0 = acc.x * r + bb.x;
        float o1 = acc.y * r + bb.y;
        float o2 = acc.z * r + bb.z;
        float o3 = acc.w * r + bb.w;
        o0 = o0 > 0.f ? o0 : (__expf(o0) - 1.0f);
        o1 = o1 > 0.f ? o1 : (__expf(o1) - 1.0f);
        o2 = o2 > 0.f ? o2 : (__expf(o2) - 1.0f);
        o3 = o3 > 0.f ? o3 : (__expf(o3) - 1.0f);

        float4 w0 = *(const float4*)&W2[cb * 2];
        float4 w1 = *(const float4*)&W2[cb * 2 + 4];
        float a0 = o0 * w0.x + o1 * w0.z + o2 * w1.x + o3 * w1.z;
        float a1 = o0 * w0.y + o1 * w0.w + o2 * w1.y + o3 * w1.w;
        a0 = warp_sum(a0);
        a1 = warp_sum(a1);
        if (lane == 0) {
            float as2 = a0 * att_src2[0] + a1 * att_src2[1];
            float ad2 = a0 * att_dst2[0] + a1 * att_dst2[1];
            g_pk2[node] = make_float4(a0, a1, as2, ad2);
            atomicMax(&sm, fenc(as2));
        }
    }
    __syncthreads();
    if (threadIdx.x == 0) atomicMax(&g_maxenc2, sm);
}

// ---------------- layer-2 aggregation + bias + log_softmax ----------------
__global__ void aggr2_kernel(const float* __restrict__ b2,
                             float* __restrict__ out, int n) {
    int node = (blockIdx.x * blockDim.x + threadIdx.x) >> 5;
    int lane = threadIdx.x & 31;
    if (node >= n) return;
    int start = g_off[node], end = start + g_deg[node];
    float ad = __ldg(&g_pk2[node]).w;
    float M = lrelu(fdec(g_maxenc2) + ad);

    float sum = 0.f, acc0 = 0.f, acc1 = 0.f;
    for (int i = start + lane; i < end; i += 32) {
        int s = __ldg(&g_src[i]);
        float4 p = __ldg(&g_pk2[s]);
        float ex = __expf(lrelu(p.z + ad) - M);
        sum += ex;
        acc0 = fmaf(ex, p.x, acc0);
        acc1 = fmaf(ex, p.y, acc1);
    }
    sum = warp_sum(sum);
    acc0 = warp_sum(acc0);
    acc1 = warp_sum(acc1);

    if (lane == 0) {
        float o0 = acc0 / (sum + EPS) + b2[0];
        float o1 = acc1 / (sum + EPS) + b2[1];
        float mx = fmaxf(o0, o1);
        float lse = mx + __logf(__expf(o0 - mx) + __expf(o1 - mx));
        out[node * 2 + 0] = o0 - lse;
        out[node * 2 + 1] = o1 - lse;
    }
}

// ---------------- launch (fork/join: GEMM1 overlaps the CSR build chain) ----------------
extern "C" void kernel_launch(void* const* d_in, const int* in_sizes, int n_in,
                              void* d_out, int out_size) {
    const float* x         = (const float*)d_in[0];
    const void*  ei        = (const void*)d_in[1];
    const float* W1        = (const float*)d_in[2];
    const float* att_src1  = (const float*)d_in[3];
    const float* att_dst1  = (const float*)d_in[4];
    const float* b1        = (const float*)d_in[5];
    const float* W2        = (const float*)d_in[6];
    const float* att_src2  = (const float*)d_in[7];
    const float* att_dst2  = (const float*)d_in[8];
    const float* b2        = (const float*)d_in[9];
    float* out             = (float*)d_out;

    int n = in_sizes[0] / 128;   // 50000
    int e = in_sizes[1] / 2;     // 800000
    int gblocks = (n + 127) / 128;   // 391

    // Lazily create side stream + fork/join events ONCE (first call = correctness
    // run, outside graph capture). No device memory involved.
    static cudaStream_t s1 = 0;
    static cudaEvent_t evFork = 0, evJoin = 0;
    static int ready = 0;
    if (!ready) {
        cudaStream_t ts; cudaEvent_t tf, tj;
        if (cudaStreamCreateWithFlags(&ts, cudaStreamNonBlocking) == cudaSuccess &&
            cudaEventCreateWithFlags(&tf, cudaEventDisableTiming) == cudaSuccess &&
            cudaEventCreateWithFlags(&tj, cudaEventDisableTiming) == cudaSuccess) {
            s1 = ts; evFork = tf; evJoin = tj;
            ready = 1;
        } else {
            ready = -1;   // fall back to fully serial on stream 0
        }
    }

    init_sniff_kernel<<<(n + 255) / 256, 256>>>((const int*)ei, in_sizes[1], n);

    if (ready == 1) {
        cudaEventRecord(evFork, 0);
        cudaStreamWaitEvent(s1, evFork, 0);
        // side stream: dense GEMM (independent of CSR)
        gemm1_kernel<<<gblocks, 256, 0, s1>>>(x, W1, att_src1, att_dst1, n);
        // main stream: CSR chain
        hist_kernel<<<512, 256>>>(ei, e);
        offsets_kernel<<<(n + 255) / 256, 256>>>(n);
        scatter_kernel<<<((e >> 1) + n + 255) / 256, 256>>>(ei, e, n);
        cudaEventRecord(evJoin, s1);
        cudaStreamWaitEvent(0, evJoin, 0);
    } else {
        gemm1_kernel<<<gblocks, 256>>>(x, W1, att_src1, att_dst1, n);
        hist_kernel<<<512, 256>>>(ei, e);
        offsets_kernel<<<(n + 255) / 256, 256>>>(n);
        scatter_kernel<<<((e >> 1) + n + 255) / 256, 256>>>(ei, e, n);
    }

    aggr1_fused_kernel<<<(n * 32 + 255) / 256, 256>>>(b1, W2, att_src2, att_dst2, n);
    aggr2_kernel<<<(n * 32 + 255) / 256, 256>>>(b2, out, n);
}